// round 1
// baseline (speedup 1.0000x reference)
#include <cuda_runtime.h>
#include <cstdint>
#include <cstddef>

// Problem constants
#define BB 128
#define TT 20
#define VV 10000
#define EE 512
#define HH 1024
#define FF 196
#define DD 512

// ---------------------------------------------------------------------------
// Device scratch (allocation-free rule: __device__ globals)
// ---------------------------------------------------------------------------
__device__ float g_a_feat[(size_t)BB * FF * DD];       // 51.4 MB
__device__ float g_x_emb[(size_t)BB * TT * EE];        // 5.2 MB
__device__ float g_gemb[(size_t)BB * TT * 4 * HH];     // 41.9 MB
__device__ float g_hall[(size_t)BB * TT * HH];         // 10.5 MB
__device__ float g_h[BB * HH];
__device__ float g_c[BB * HH];
__device__ float g_z[BB * DD];
__device__ float g_z0[BB * DD];
__device__ float g_ah[BB * DD];
__device__ float g_scores[BB * FF];
__device__ float g_alpha[BB * FF];
__device__ float g_gates[BB * 4 * HH];

// ---------------------------------------------------------------------------
// Generic fp32 GEMM:  C[M,N] = A[M,K] * B[N,K]^T  (+ epilogue per MODE)
//   MODE 0: C = acc + bias[n] (+ bias2[n] if non-null)
//   MODE 1: gates GEMM. A is split [z | h] at k=512 (ldA 512 / 1024),
//           B is split [W_ih[:, :512] | W_hh] at k=512 (both row stride 1024).
//           C = acc + Cadd[m*ldadd + n]
//   MODE 2: fc GEMM with length mask: row m -> (b = m/Tdim, t = m%Tdim),
//           C = lengths[b] >= t ? acc + bias[n] : 0
// Tiles: 256 threads, BM x BN block tile, TM x TN per-thread microtile,
// shared tiles stored K-major-transposed for vectorized LDS.
// ---------------------------------------------------------------------------
template<int BM, int BN, int BK, int TM, int TN, int MODE>
__global__ void __launch_bounds__(256, 1)
gemm_tn(const float* __restrict__ A, int lda,
        const float* __restrict__ A2,
        const float* __restrict__ Bm, int ldb,
        const float* __restrict__ B2,
        const float* __restrict__ bias, const float* __restrict__ bias2,
        const float* __restrict__ Cadd, int ldadd,
        float* __restrict__ C, int ldc,
        int M, int N, int K,
        const int* __restrict__ lengths, int Tdim)
{
    __shared__ __align__(16) float As[BK][BM];
    __shared__ __align__(16) float Bs[BK][BN];

    const int tid = threadIdx.x;
    constexpr int TX = BN / TN;
    const int tx = tid % TX;
    const int ty = tid / TX;
    const long m0 = (long)blockIdx.x * BM;
    const long n0 = (long)blockIdx.y * BN;

    float acc[TM][TN];
#pragma unroll
    for (int i = 0; i < TM; i++)
#pragma unroll
        for (int j = 0; j < TN; j++) acc[i][j] = 0.f;

    for (int k0 = 0; k0 < K; k0 += BK) {
        // ---- load A tile (transposed into shared) ----
        for (int idx = tid; idx < BM * (BK / 4); idx += 256) {
            int m = idx / (BK / 4), kq = idx % (BK / 4);
            long gm = m0 + m;
            int gk = k0 + kq * 4;
            float4 v = make_float4(0.f, 0.f, 0.f, 0.f);
            if (gm < M) {
                if (MODE == 1) {
                    v = (gk < 512)
                        ? *(const float4*)(A  + gm * 512  + gk)
                        : *(const float4*)(A2 + gm * 1024 + (gk - 512));
                } else {
                    v = *(const float4*)(A + gm * (long)lda + gk);
                }
            }
            As[kq * 4 + 0][m] = v.x;
            As[kq * 4 + 1][m] = v.y;
            As[kq * 4 + 2][m] = v.z;
            As[kq * 4 + 3][m] = v.w;
        }
        // ---- load B tile (transposed into shared) ----
        for (int idx = tid; idx < BN * (BK / 4); idx += 256) {
            int n = idx / (BK / 4), kq = idx % (BK / 4);
            long gn = n0 + n;
            int gk = k0 + kq * 4;
            float4 v = make_float4(0.f, 0.f, 0.f, 0.f);
            if (gn < N) {
                if (MODE == 1) {
                    v = (gk < 512)
                        ? *(const float4*)(Bm + gn * 1024 + gk)
                        : *(const float4*)(B2 + gn * 1024 + (gk - 512));
                } else {
                    v = *(const float4*)(Bm + gn * (long)ldb + gk);
                }
            }
            Bs[kq * 4 + 0][n] = v.x;
            Bs[kq * 4 + 1][n] = v.y;
            Bs[kq * 4 + 2][n] = v.z;
            Bs[kq * 4 + 3][n] = v.w;
        }
        __syncthreads();

#pragma unroll
        for (int kk = 0; kk < BK; kk++) {
            float a[TM], b[TN];
            if constexpr (TM == 4) {
                float4 t = *(const float4*)&As[kk][ty * TM];
                a[0] = t.x; a[1] = t.y; a[2] = t.z; a[3] = t.w;
            } else {
                float2 t = *(const float2*)&As[kk][ty * TM];
                a[0] = t.x; a[1] = t.y;
            }
            if constexpr (TN == 4) {
                float4 t = *(const float4*)&Bs[kk][tx * TN];
                b[0] = t.x; b[1] = t.y; b[2] = t.z; b[3] = t.w;
            } else {
                float2 t = *(const float2*)&Bs[kk][tx * TN];
                b[0] = t.x; b[1] = t.y;
            }
#pragma unroll
            for (int i = 0; i < TM; i++)
#pragma unroll
                for (int j = 0; j < TN; j++)
                    acc[i][j] = fmaf(a[i], b[j], acc[i][j]);
        }
        __syncthreads();
    }

    // ---- epilogue ----
#pragma unroll
    for (int i = 0; i < TM; i++) {
        long gm = m0 + ty * TM + i;
        if (gm >= M) continue;
#pragma unroll
        for (int j = 0; j < TN; j++) {
            long gn = n0 + tx * TN + j;
            if (gn >= N) continue;
            float v = acc[i][j];
            if (MODE == 0) {
                if (bias)  v += bias[gn];
                if (bias2) v += bias2[gn];
            } else if (MODE == 1) {
                v += Cadd[gm * (long)ldadd + gn];
            } else {  // MODE 2: fc + length mask
                v += bias[gn];
                int bb = (int)(gm / Tdim);
                int tt = (int)(gm % Tdim);
                if (lengths[bb] < tt) v = 0.f;
            }
            C[gm * (long)ldc + gn] = v;
        }
    }
}

// ---------------------------------------------------------------------------
// Embedding gather: x_emb[r, :] = emb[captions[r], :]
// ---------------------------------------------------------------------------
__global__ void gather_kernel(const int* __restrict__ cap,
                              const float* __restrict__ emb,
                              float* __restrict__ xe)
{
    int r = blockIdx.x;
    int i = threadIdx.x;  // 128 threads, float4 each -> 512 floats
    const float4* src = (const float4*)(emb + (size_t)cap[r] * EE);
    ((float4*)(xe + (size_t)r * EE))[i] = src[i];
}

// ---------------------------------------------------------------------------
// scores[b,f] = sum_k relu(a_feat[b,f,k] + a_h[b,k]) * w_a[k] + b_a
// One warp per (b,f) row.
// ---------------------------------------------------------------------------
__global__ void scores_kernel(const float* __restrict__ a_feat,
                              const float* __restrict__ a_h,
                              const float* __restrict__ w_a,
                              const float* __restrict__ b_a,
                              float* __restrict__ scores)
{
    int r = blockIdx.x * blockDim.y + threadIdx.y;
    if (r >= BB * FF) return;
    int b = r / FF;
    const float4* af = (const float4*)(a_feat + (size_t)r * DD);
    const float4* ah = (const float4*)(a_h + (size_t)b * DD);
    const float4* wv = (const float4*)w_a;
    float s = 0.f;
#pragma unroll 2
    for (int k = threadIdx.x; k < DD / 4; k += 32) {
        float4 a = af[k];
        float4 h = ah[k];
        float4 w = wv[k];
        s += fmaxf(a.x + h.x, 0.f) * w.x
           + fmaxf(a.y + h.y, 0.f) * w.y
           + fmaxf(a.z + h.z, 0.f) * w.z
           + fmaxf(a.w + h.w, 0.f) * w.w;
    }
#pragma unroll
    for (int o = 16; o; o >>= 1) s += __shfl_down_sync(0xffffffffu, s, o);
    if (threadIdx.x == 0) scores[r] = s + b_a[0];
}

// ---------------------------------------------------------------------------
// Softmax over F=196 per batch row. One block per b.
// ---------------------------------------------------------------------------
__global__ void softmax_kernel(const float* __restrict__ scores,
                               float* __restrict__ alpha)
{
    int b = blockIdx.x;
    int tid = threadIdx.x;  // 256
    __shared__ float redm[8];
    __shared__ float reds[8];
    __shared__ float bmax, bsum;

    float v = (tid < FF) ? scores[b * FF + tid] : -3.0e38f;
    float m = v;
#pragma unroll
    for (int o = 16; o; o >>= 1) m = fmaxf(m, __shfl_xor_sync(0xffffffffu, m, o));
    if ((tid & 31) == 0) redm[tid >> 5] = m;
    __syncthreads();
    if (tid == 0) {
        float x = redm[0];
        for (int w = 1; w < 8; w++) x = fmaxf(x, redm[w]);
        bmax = x;
    }
    __syncthreads();

    float e = (tid < FF) ? expf(v - bmax) : 0.f;
    float s = e;
#pragma unroll
    for (int o = 16; o; o >>= 1) s += __shfl_xor_sync(0xffffffffu, s, o);
    if ((tid & 31) == 0) reds[tid >> 5] = s;
    __syncthreads();
    if (tid == 0) {
        float x = 0.f;
        for (int w = 0; w < 8; w++) x += reds[w];
        bsum = x;
    }
    __syncthreads();
    if (tid < FF) alpha[b * FF + tid] = e / bsum;
}

// ---------------------------------------------------------------------------
// z[b,d] = sum_f w(f) * feature[b,f,d]   (w = alpha row, or 1/F for z0)
// grid (B, D/128), 128 threads; coalesced over d.
// ---------------------------------------------------------------------------
__global__ void zcalc_kernel(const float* __restrict__ feature,
                             const float* __restrict__ alpha,
                             float* __restrict__ z)
{
    int b = blockIdx.x;
    int d = blockIdx.y * 128 + threadIdx.x;
    __shared__ float sal[FF];
    for (int f = threadIdx.x; f < FF; f += 128)
        sal[f] = alpha ? alpha[b * FF + f] : (1.0f / FF);
    __syncthreads();
    const float* fp = feature + (size_t)b * FF * DD + d;
    float s0 = 0.f, s1 = 0.f, s2 = 0.f, s3 = 0.f;
    int f = 0;
    for (; f + 4 <= FF; f += 4) {
        s0 += sal[f + 0] * fp[(size_t)(f + 0) * DD];
        s1 += sal[f + 1] * fp[(size_t)(f + 1) * DD];
        s2 += sal[f + 2] * fp[(size_t)(f + 2) * DD];
        s3 += sal[f + 3] * fp[(size_t)(f + 3) * DD];
    }
    for (; f < FF; f++) s0 += sal[f] * fp[(size_t)f * DD];
    z[b * DD + d] = (s0 + s1) + (s2 + s3);
}

// ---------------------------------------------------------------------------
// LSTM pointwise update. gates layout [B, 4H] with i|f|g|o blocks of H.
// Stores UNMASKED h_new into h_all (mask is applied in the fc epilogue),
// carries masked h/c for the recurrence.
// ---------------------------------------------------------------------------
__device__ __forceinline__ float sigmoidf_(float x) { return 1.f / (1.f + expf(-x)); }

__global__ void lstm_kernel(const float* __restrict__ gates,
                            const int* __restrict__ lengths, int t,
                            float* __restrict__ h, float* __restrict__ c,
                            float* __restrict__ hall)
{
    int idx = blockIdx.x * blockDim.x + threadIdx.x;
    if (idx >= BB * HH) return;
    int b = idx >> 10;           // H = 1024
    int hh = idx & (HH - 1);
    const float* g = gates + (size_t)b * 4 * HH;
    float ii = sigmoidf_(g[hh]);
    float ff = sigmoidf_(g[HH + hh]);
    float gg = tanhf(g[2 * HH + hh]);
    float oo = sigmoidf_(g[3 * HH + hh]);
    float cn = ff * c[idx] + ii * gg;
    float hn = oo * tanhf(cn);
    hall[((size_t)b * TT + t) * HH + hh] = hn;
    if (lengths[b] >= t) {
        h[idx] = hn;
        c[idx] = cn;
    }
}

// ---------------------------------------------------------------------------
// Host orchestration
// ---------------------------------------------------------------------------
extern "C" void kernel_launch(void* const* d_in, const int* in_sizes, int n_in,
                              void* d_out, int out_size)
{
    const float* feature = (const float*)d_in[0];
    const int*   captions = (const int*)d_in[1];
    const int*   lengths = (const int*)d_in[2];
    const float* emb    = (const float*)d_in[3];
    const float* W_ih   = (const float*)d_in[4];
    const float* b_ih   = (const float*)d_in[5];
    const float* W_hh   = (const float*)d_in[6];
    const float* b_hh   = (const float*)d_in[7];
    const float* W_fc   = (const float*)d_in[8];
    const float* b_fc   = (const float*)d_in[9];
    const float* W_h2a  = (const float*)d_in[10];
    const float* b_h2a  = (const float*)d_in[11];
    const float* W_f2a  = (const float*)d_in[12];
    const float* b_f2a  = (const float*)d_in[13];
    const float* W_a2a  = (const float*)d_in[14];
    const float* b_a2a  = (const float*)d_in[15];
    float* out = (float*)d_out;

    float *a_feat, *x_e, *gemb, *hall, *h, *c, *z, *z0, *ah, *scores, *alpha, *gates;
    cudaGetSymbolAddress((void**)&a_feat, g_a_feat);
    cudaGetSymbolAddress((void**)&x_e,    g_x_emb);
    cudaGetSymbolAddress((void**)&gemb,   g_gemb);
    cudaGetSymbolAddress((void**)&hall,   g_hall);
    cudaGetSymbolAddress((void**)&h,      g_h);
    cudaGetSymbolAddress((void**)&c,      g_c);
    cudaGetSymbolAddress((void**)&z,      g_z);
    cudaGetSymbolAddress((void**)&z0,     g_z0);
    cudaGetSymbolAddress((void**)&ah,     g_ah);
    cudaGetSymbolAddress((void**)&scores, g_scores);
    cudaGetSymbolAddress((void**)&alpha,  g_alpha);
    cudaGetSymbolAddress((void**)&gates,  g_gates);

    // h, c = 0
    cudaMemsetAsync(h, 0, (size_t)BB * HH * sizeof(float));
    cudaMemsetAsync(c, 0, (size_t)BB * HH * sizeof(float));

    // x_emb gather
    gather_kernel<<<BB * TT, 128>>>(captions, emb, x_e);

    // a_feat = feature @ W_f2a^T + b_f2a       [B*F, D] x [D, D]
    gemm_tn<64, 64, 16, 4, 4, 0><<<dim3((BB * FF) / 64, DD / 64), 256>>>(
        feature, DD, nullptr, W_f2a, DD, nullptr,
        b_f2a, nullptr, nullptr, 0,
        a_feat, DD, BB * FF, DD, DD, nullptr, 0);

    // g_emb = x_emb @ W_ih[:, D:]^T + b_ih + b_hh   [B*T, E] x [4H, E]
    gemm_tn<64, 64, 16, 4, 4, 0><<<dim3((BB * TT) / 64, (4 * HH) / 64), 256>>>(
        x_e, EE, nullptr, W_ih + DD, DD + EE, nullptr,
        b_ih, b_hh, nullptr, 0,
        gemb, 4 * HH, BB * TT, 4 * HH, EE, nullptr, 0);

    // z0 = mean(feature, axis=1)
    zcalc_kernel<<<dim3(BB, DD / 128), 128>>>(feature, nullptr, z0);

    // Sequential recurrence
    for (int t = 0; t < TT; t++) {
        const float* zptr = z0;
        if (t > 0) {
            // a_h = h @ W_h2a^T + b_h2a     [B, H] x [D, H]
            gemm_tn<32, 32, 16, 2, 2, 0><<<dim3(BB / 32, DD / 32), 256>>>(
                h, HH, nullptr, W_h2a, HH, nullptr,
                b_h2a, nullptr, nullptr, 0,
                ah, DD, BB, DD, HH, nullptr, 0);

            scores_kernel<<<(BB * FF + 7) / 8, dim3(32, 8)>>>(a_feat, ah, W_a2a, b_a2a, scores);
            softmax_kernel<<<BB, 256>>>(scores, alpha);
            zcalc_kernel<<<dim3(BB, DD / 128), 128>>>(feature, alpha, z);
            zptr = z;
        }

        // gates = g_emb[:, t, :] + [z | h] @ [W_ih[:, :D] | W_hh]^T
        gemm_tn<32, 64, 16, 2, 4, 1><<<dim3(BB / 32, (4 * HH) / 64), 256>>>(
            zptr, 0, h, W_ih, 0, W_hh,
            nullptr, nullptr, gemb + (size_t)t * 4 * HH, TT * 4 * HH,
            gates, 4 * HH, BB, 4 * HH, DD + HH, nullptr, 0);

        lstm_kernel<<<(BB * HH + 255) / 256, 256>>>(gates, lengths, t, h, c, hall);
    }

    // preds = (h_all @ W_fc^T + b_fc) * mask     [B*T, H] x [V, H]
    gemm_tn<64, 64, 16, 4, 4, 2><<<dim3((BB * TT) / 64, (VV + 63) / 64), 256>>>(
        hall, HH, nullptr, W_fc, HH, nullptr,
        b_fc, nullptr, nullptr, 0,
        out, VV, BB * TT, VV, HH, lengths, TT);
}

// round 2
// speedup vs baseline: 1.1256x; 1.1256x over previous
#include <cuda_runtime.h>
#include <cstdint>
#include <cstddef>

// Problem constants
#define BB 128
#define TT 20
#define VV 10000
#define EE 512
#define HH 1024
#define FF 196
#define DD 512

// ---------------------------------------------------------------------------
// Device scratch (allocation-free rule: __device__ globals)
// ---------------------------------------------------------------------------
__device__ float g_a_feat[(size_t)BB * FF * DD];       // 51.4 MB
__device__ float g_x_emb[(size_t)BB * TT * EE];        // 5.2 MB
__device__ float g_gemb[(size_t)BB * TT * 4 * HH];     // 41.9 MB
__device__ float g_hall[(size_t)BB * TT * HH];         // 10.5 MB
__device__ float g_h[BB * HH];
__device__ float g_c[BB * HH];
__device__ float g_z[BB * DD];
__device__ float g_z0[BB * DD];
__device__ float g_ah[BB * DD];
__device__ float g_gates[BB * 4 * HH];
__device__ int   g_rowidx[BB * TT];
__device__ int   g_mact[1];

// ---------------------------------------------------------------------------
// Double-buffered fp32 GEMM:  C[M,N] = A[M,K] * B[N,K]^T  (+ epilogue by MODE)
//   MODE 0: C = acc + bias[n] (+ bias2[n] if non-null)
//   MODE 1: gates GEMM. A split [z | h] at k=512 (ldA 512 / 1024),
//           B split [W_ih[:, :512] | W_hh] (both row stride 1024).
//           C = acc + Cadd[gm*ldadd + gn]
//   MODE 3: fc GEMM over compacted active rows: A row = rowidx[gm], gm < *mact;
//           C[rowidx[gm]*ldc + gn] = acc + bias[gn]
// 256 threads, (BM/TM)x(BN/TN) must be 16x16. BM*BK and BN*BK >= 1024.
// ---------------------------------------------------------------------------
template<int BM, int BN, int BK, int TM, int TN, int MODE>
__global__ void __launch_bounds__(256)
gemm2(const float* __restrict__ A, int lda,
      const float* __restrict__ A2,
      const float* __restrict__ Bm, int ldb,
      const float* __restrict__ B2,
      const float* __restrict__ bias, const float* __restrict__ bias2,
      const float* __restrict__ Cadd, int ldadd,
      float* __restrict__ C, int ldc,
      int M, int N, int K,
      const int* __restrict__ rowidx, const int* __restrict__ mact)
{
    constexpr int LA = (BM * BK) / (4 * 256);
    constexpr int LB = (BN * BK) / (4 * 256);
    static_assert(LA >= 1 && LB >= 1, "tile too small");
    static_assert((BM / TM) * (BN / TN) == 256, "thread grid");

    __shared__ __align__(16) float As[2][BK][BM];
    __shared__ __align__(16) float Bs[2][BK][BN];
    __shared__ int sridx[BM];

    const int tid = threadIdx.x;
    constexpr int TX = BN / TN;
    const int tx = tid % TX;
    const int ty = tid / TX;
    const long m0 = (long)blockIdx.x * BM;
    const long n0 = (long)blockIdx.y * BN;

    int Mact = M;
    if (MODE == 3) {
        Mact = *mact;
        if (m0 >= Mact) return;
        for (int i = tid; i < BM; i += 256) {
            long gm = m0 + i;
            sridx[i] = (gm < Mact) ? rowidx[gm] : -1;
        }
        __syncthreads();
    }

    float acc[TM][TN];
#pragma unroll
    for (int i = 0; i < TM; i++)
#pragma unroll
        for (int j = 0; j < TN; j++) acc[i][j] = 0.f;

    float4 pa[LA], pb[LB];

    auto loadA = [&](int k0) {
#pragma unroll
        for (int l = 0; l < LA; l++) {
            int idx = tid + l * 256;
            int m = idx / (BK / 4), kq = idx % (BK / 4);
            long gm = m0 + m;
            int gk = k0 + kq * 4;
            float4 v = make_float4(0.f, 0.f, 0.f, 0.f);
            if (MODE == 1) {
                v = (gk < 512)
                    ? *(const float4*)(A  + gm * 512  + gk)
                    : *(const float4*)(A2 + gm * 1024 + (gk - 512));
            } else if (MODE == 3) {
                int ar = sridx[m];
                if (ar >= 0) v = *(const float4*)(A + (size_t)ar * lda + gk);
            } else {
                if (gm < M) v = *(const float4*)(A + gm * (long)lda + gk);
            }
            pa[l] = v;
        }
    };
    auto loadB = [&](int k0) {
#pragma unroll
        for (int l = 0; l < LB; l++) {
            int idx = tid + l * 256;
            int n = idx / (BK / 4), kq = idx % (BK / 4);
            long gn = n0 + n;
            int gk = k0 + kq * 4;
            float4 v = make_float4(0.f, 0.f, 0.f, 0.f);
            if (MODE == 1) {
                v = (gk < 512)
                    ? *(const float4*)(Bm + gn * 1024 + gk)
                    : *(const float4*)(B2 + gn * 1024 + (gk - 512));
            } else {
                if (gn < N) v = *(const float4*)(Bm + gn * (long)ldb + gk);
            }
            pb[l] = v;
        }
    };
    auto storeA = [&](int buf) {
#pragma unroll
        for (int l = 0; l < LA; l++) {
            int idx = tid + l * 256;
            int m = idx / (BK / 4), kq = idx % (BK / 4);
            As[buf][kq * 4 + 0][m] = pa[l].x;
            As[buf][kq * 4 + 1][m] = pa[l].y;
            As[buf][kq * 4 + 2][m] = pa[l].z;
            As[buf][kq * 4 + 3][m] = pa[l].w;
        }
    };
    auto storeB = [&](int buf) {
#pragma unroll
        for (int l = 0; l < LB; l++) {
            int idx = tid + l * 256;
            int n = idx / (BK / 4), kq = idx % (BK / 4);
            Bs[buf][kq * 4 + 0][n] = pb[l].x;
            Bs[buf][kq * 4 + 1][n] = pb[l].y;
            Bs[buf][kq * 4 + 2][n] = pb[l].z;
            Bs[buf][kq * 4 + 3][n] = pb[l].w;
        }
    };

    loadA(0); loadB(0);
    storeA(0); storeB(0);
    __syncthreads();

    int buf = 0;
    for (int k0 = 0; k0 < K; k0 += BK) {
        const bool has_next = (k0 + BK) < K;
        if (has_next) { loadA(k0 + BK); loadB(k0 + BK); }

#pragma unroll
        for (int kk = 0; kk < BK; kk++) {
            float a[TM], bf[TN];
            if constexpr (TM == 8) {
                float4 t0 = *(const float4*)&As[buf][kk][ty * 8];
                float4 t1 = *(const float4*)&As[buf][kk][ty * 8 + 4];
                a[0]=t0.x; a[1]=t0.y; a[2]=t0.z; a[3]=t0.w;
                a[4]=t1.x; a[5]=t1.y; a[6]=t1.z; a[7]=t1.w;
            } else if constexpr (TM == 4) {
                float4 t0 = *(const float4*)&As[buf][kk][ty * 4];
                a[0]=t0.x; a[1]=t0.y; a[2]=t0.z; a[3]=t0.w;
            } else {
                float2 t0 = *(const float2*)&As[buf][kk][ty * 2];
                a[0]=t0.x; a[1]=t0.y;
            }
            if constexpr (TN == 8) {
                float4 t0 = *(const float4*)&Bs[buf][kk][tx * 8];
                float4 t1 = *(const float4*)&Bs[buf][kk][tx * 8 + 4];
                bf[0]=t0.x; bf[1]=t0.y; bf[2]=t0.z; bf[3]=t0.w;
                bf[4]=t1.x; bf[5]=t1.y; bf[6]=t1.z; bf[7]=t1.w;
            } else if constexpr (TN == 4) {
                float4 t0 = *(const float4*)&Bs[buf][kk][tx * 4];
                bf[0]=t0.x; bf[1]=t0.y; bf[2]=t0.z; bf[3]=t0.w;
            } else {
                float2 t0 = *(const float2*)&Bs[buf][kk][tx * 2];
                bf[0]=t0.x; bf[1]=t0.y;
            }
#pragma unroll
            for (int i = 0; i < TM; i++)
#pragma unroll
                for (int j = 0; j < TN; j++)
                    acc[i][j] = fmaf(a[i], bf[j], acc[i][j]);
        }

        if (has_next) {
            storeA(buf ^ 1); storeB(buf ^ 1);
            __syncthreads();
            buf ^= 1;
        }
    }

    // ---- epilogue ----
#pragma unroll
    for (int i = 0; i < TM; i++) {
        long gm = m0 + ty * TM + i;
        float* crow;
        if (MODE == 3) {
            if (gm >= Mact) continue;
            crow = C + (size_t)sridx[ty * TM + i] * ldc;
        } else {
            if (gm >= M) continue;
            crow = C + gm * (long)ldc;
        }
#pragma unroll
        for (int j = 0; j < TN; j++) {
            long gn = n0 + tx * TN + j;
            if (gn >= N) continue;
            float v = acc[i][j];
            if (MODE == 0) {
                if (bias)  v += bias[gn];
                if (bias2) v += bias2[gn];
            } else if (MODE == 1) {
                v += Cadd[gm * (long)ldadd + gn];
            } else {  // MODE 3
                v += bias[gn];
            }
            crow[gn] = v;
        }
    }
}

// ---------------------------------------------------------------------------
// Compaction of active (b,t) rows: active iff t <= lengths[b].
// ---------------------------------------------------------------------------
__global__ void compact_rows(const int* __restrict__ lengths,
                             int* __restrict__ rowidx, int* __restrict__ mact)
{
    __shared__ int off[BB + 1];
    int b = threadIdx.x;  // 128 threads
    int cnt = min(lengths[b] + 1, TT);
    __shared__ int cnts[BB];
    cnts[b] = cnt;
    __syncthreads();
    if (b == 0) {
        int s = 0;
        for (int i = 0; i < BB; i++) { off[i] = s; s += cnts[i]; }
        off[BB] = s;
        *mact = s;
    }
    __syncthreads();
    int o = off[b];
    for (int j = 0; j < cnt; j++) rowidx[o + j] = b * TT + j;
}

// Zero output rows where lengths[b] < t (out poisoned to 0xAA by harness).
__global__ void zero_masked(const int* __restrict__ lengths, float* __restrict__ out)
{
    int r = blockIdx.x;
    int b = r / TT, t = r % TT;
    if (lengths[b] >= t) return;
    float4 zz = make_float4(0.f, 0.f, 0.f, 0.f);
    float4* row = (float4*)(out + (size_t)r * VV);
    for (int i = threadIdx.x; i < VV / 4; i += blockDim.x) row[i] = zz;
}

// ---------------------------------------------------------------------------
// Embedding gather: x_emb[r, :] = emb[captions[r], :]
// ---------------------------------------------------------------------------
__global__ void gather_kernel(const int* __restrict__ cap,
                              const float* __restrict__ emb,
                              float* __restrict__ xe)
{
    int r = blockIdx.x;
    int i = threadIdx.x;  // 128 threads, float4 each -> 512 floats
    const float4* src = (const float4*)(emb + (size_t)cap[r] * EE);
    ((float4*)(xe + (size_t)r * EE))[i] = src[i];
}

// ---------------------------------------------------------------------------
// Fused attention: per batch row b (one block, 256 threads):
//   scores[f] = sum_k relu(a_feat[b,f,k] + a_h[b,k]) * w_a[k] + b_a
//   alpha = softmax(scores);  z[b,d] = sum_f alpha[f] * feature[b,f,d]
// ---------------------------------------------------------------------------
__global__ void __launch_bounds__(256)
attn_fused(const float* __restrict__ a_feat,
           const float* __restrict__ ah,
           const float* __restrict__ w_a,
           const float* __restrict__ b_a,
           const float* __restrict__ feature,
           float* __restrict__ z)
{
    int b = blockIdx.x;
    int tid = threadIdx.x;
    int warp = tid >> 5, lane = tid & 31;
    __shared__ __align__(16) float s_ah[DD];
    __shared__ __align__(16) float s_w[DD];
    __shared__ float s_sc[FF];
    __shared__ float red[8];
    __shared__ float bmax, bsum;

    for (int i = tid; i < DD / 4; i += 256) {
        ((float4*)s_ah)[i] = ((const float4*)(ah + (size_t)b * DD))[i];
        ((float4*)s_w)[i]  = ((const float4*)w_a)[i];
    }
    __syncthreads();

    float ba = b_a[0];
    for (int f = warp; f < FF; f += 8) {
        const float4* af = (const float4*)(a_feat + ((size_t)b * FF + f) * DD);
        float s = 0.f;
#pragma unroll 4
        for (int k = lane; k < DD / 4; k += 32) {
            float4 a = af[k];
            float4 h4 = ((const float4*)s_ah)[k];
            float4 w4 = ((const float4*)s_w)[k];
            s += fmaxf(a.x + h4.x, 0.f) * w4.x
               + fmaxf(a.y + h4.y, 0.f) * w4.y
               + fmaxf(a.z + h4.z, 0.f) * w4.z
               + fmaxf(a.w + h4.w, 0.f) * w4.w;
        }
#pragma unroll
        for (int o = 16; o; o >>= 1) s += __shfl_down_sync(0xffffffffu, s, o);
        if (lane == 0) s_sc[f] = s + ba;
    }
    __syncthreads();

    // softmax over FF=196
    float v = (tid < FF) ? s_sc[tid] : -3.0e38f;
    float m = v;
#pragma unroll
    for (int o = 16; o; o >>= 1) m = fmaxf(m, __shfl_xor_sync(0xffffffffu, m, o));
    if (lane == 0) red[warp] = m;
    __syncthreads();
    if (tid == 0) {
        float x = red[0];
        for (int w = 1; w < 8; w++) x = fmaxf(x, red[w]);
        bmax = x;
    }
    __syncthreads();
    float e = (tid < FF) ? expf(v - bmax) : 0.f;
    float s = e;
#pragma unroll
    for (int o = 16; o; o >>= 1) s += __shfl_xor_sync(0xffffffffu, s, o);
    if (lane == 0) red[warp] = s;
    __syncthreads();
    if (tid == 0) {
        float x = 0.f;
        for (int w = 0; w < 8; w++) x += red[w];
        bsum = x;
    }
    __syncthreads();
    if (tid < FF) s_sc[tid] = e / bsum;
    __syncthreads();

    // z[b, d] = sum_f alpha[f] * feature[b, f, d]
    const float* fp = feature + (size_t)b * FF * DD;
    for (int d = tid; d < DD; d += 256) {
        float s0 = 0.f, s1 = 0.f, s2 = 0.f, s3 = 0.f;
        for (int f = 0; f < FF; f += 4) {     // FF = 196 divisible by 4
            s0 += s_sc[f + 0] * fp[(size_t)(f + 0) * DD + d];
            s1 += s_sc[f + 1] * fp[(size_t)(f + 1) * DD + d];
            s2 += s_sc[f + 2] * fp[(size_t)(f + 2) * DD + d];
            s3 += s_sc[f + 3] * fp[(size_t)(f + 3) * DD + d];
        }
        z[(size_t)b * DD + d] = (s0 + s1) + (s2 + s3);
    }
}

// ---------------------------------------------------------------------------
// z0[b,d] = mean over f of feature[b,f,d]
// ---------------------------------------------------------------------------
__global__ void zmean_kernel(const float* __restrict__ feature,
                             float* __restrict__ z)
{
    int b = blockIdx.x;
    int d = blockIdx.y * 128 + threadIdx.x;
    const float* fp = feature + (size_t)b * FF * DD + d;
    float s0 = 0.f, s1 = 0.f, s2 = 0.f, s3 = 0.f;
    for (int f = 0; f < FF; f += 4) {
        s0 += fp[(size_t)(f + 0) * DD];
        s1 += fp[(size_t)(f + 1) * DD];
        s2 += fp[(size_t)(f + 2) * DD];
        s3 += fp[(size_t)(f + 3) * DD];
    }
    z[b * DD + d] = ((s0 + s1) + (s2 + s3)) * (1.0f / FF);
}

// ---------------------------------------------------------------------------
// LSTM pointwise update.
// ---------------------------------------------------------------------------
__device__ __forceinline__ float sigmoidf_(float x) { return 1.f / (1.f + expf(-x)); }

__global__ void lstm_kernel(const float* __restrict__ gates,
                            const int* __restrict__ lengths, int t,
                            float* __restrict__ h, float* __restrict__ c,
                            float* __restrict__ hall)
{
    int idx = blockIdx.x * blockDim.x + threadIdx.x;
    if (idx >= BB * HH) return;
    int b = idx >> 10;           // H = 1024
    int hh = idx & (HH - 1);
    const float* g = gates + (size_t)b * 4 * HH;
    float ii = sigmoidf_(g[hh]);
    float ff = sigmoidf_(g[HH + hh]);
    float gg = tanhf(g[2 * HH + hh]);
    float oo = sigmoidf_(g[3 * HH + hh]);
    float cn = ff * c[idx] + ii * gg;
    float hn = oo * tanhf(cn);
    hall[((size_t)b * TT + t) * HH + hh] = hn;
    if (lengths[b] >= t) {
        h[idx] = hn;
        c[idx] = cn;
    }
}

// ---------------------------------------------------------------------------
// Host orchestration
// ---------------------------------------------------------------------------
extern "C" void kernel_launch(void* const* d_in, const int* in_sizes, int n_in,
                              void* d_out, int out_size)
{
    const float* feature = (const float*)d_in[0];
    const int*   captions = (const int*)d_in[1];
    const int*   lengths = (const int*)d_in[2];
    const float* emb    = (const float*)d_in[3];
    const float* W_ih   = (const float*)d_in[4];
    const float* b_ih   = (const float*)d_in[5];
    const float* W_hh   = (const float*)d_in[6];
    const float* b_hh   = (const float*)d_in[7];
    const float* W_fc   = (const float*)d_in[8];
    const float* b_fc   = (const float*)d_in[9];
    const float* W_h2a  = (const float*)d_in[10];
    const float* b_h2a  = (const float*)d_in[11];
    const float* W_f2a  = (const float*)d_in[12];
    const float* b_f2a  = (const float*)d_in[13];
    const float* W_a2a  = (const float*)d_in[14];
    const float* b_a2a  = (const float*)d_in[15];
    float* out = (float*)d_out;

    float *a_feat, *x_e, *gemb, *hall, *h, *c, *z, *z0, *ah, *gates;
    int *rowidx, *mact;
    cudaGetSymbolAddress((void**)&a_feat, g_a_feat);
    cudaGetSymbolAddress((void**)&x_e,    g_x_emb);
    cudaGetSymbolAddress((void**)&gemb,   g_gemb);
    cudaGetSymbolAddress((void**)&hall,   g_hall);
    cudaGetSymbolAddress((void**)&h,      g_h);
    cudaGetSymbolAddress((void**)&c,      g_c);
    cudaGetSymbolAddress((void**)&z,      g_z);
    cudaGetSymbolAddress((void**)&z0,     g_z0);
    cudaGetSymbolAddress((void**)&ah,     g_ah);
    cudaGetSymbolAddress((void**)&gates,  g_gates);
    cudaGetSymbolAddress((void**)&rowidx, g_rowidx);
    cudaGetSymbolAddress((void**)&mact,   g_mact);

    cudaMemsetAsync(h, 0, (size_t)BB * HH * sizeof(float));
    cudaMemsetAsync(c, 0, (size_t)BB * HH * sizeof(float));

    gather_kernel<<<BB * TT, 128>>>(captions, emb, x_e);
    compact_rows<<<1, BB>>>(lengths, rowidx, mact);

    // a_feat = feature @ W_f2a^T + b_f2a      [25088, 512] x [512, 512]
    gemm2<128, 128, 16, 8, 8, 0><<<dim3(196, 4), 256>>>(
        feature, DD, nullptr, W_f2a, DD, nullptr,
        b_f2a, nullptr, nullptr, 0,
        a_feat, DD, BB * FF, DD, DD, nullptr, nullptr);

    // g_emb = x_emb @ W_ih[:, D:]^T + b_ih + b_hh   [2560, 512] x [4096, 512]
    gemm2<128, 128, 16, 8, 8, 0><<<dim3(20, 32), 256>>>(
        x_e, EE, nullptr, W_ih + DD, DD + EE, nullptr,
        b_ih, b_hh, nullptr, 0,
        gemb, 4 * HH, BB * TT, 4 * HH, EE, nullptr, nullptr);

    zmean_kernel<<<dim3(BB, DD / 128), 128>>>(feature, z0);

    for (int t = 0; t < TT; t++) {
        const float* zptr = z0;
        if (t > 0) {
            // a_h = h @ W_h2a^T + b_h2a     [128, 1024] x [512, 1024]
            gemm2<32, 32, 32, 2, 2, 0><<<dim3(4, 16), 256>>>(
                h, HH, nullptr, W_h2a, HH, nullptr,
                b_h2a, nullptr, nullptr, 0,
                ah, DD, BB, DD, HH, nullptr, nullptr);

            attn_fused<<<BB, 256>>>(a_feat, ah, W_a2a, b_a2a, feature, z);
            zptr = z;
        }

        // gates = g_emb[:, t, :] + [z | h] @ [W_ih[:, :D] | W_hh]^T
        gemm2<64, 64, 16, 4, 4, 1><<<dim3(2, 64), 256>>>(
            zptr, 0, h, W_ih, 0, W_hh,
            nullptr, nullptr, gemb + (size_t)t * 4 * HH, TT * 4 * HH,
            gates, 4 * HH, BB, 4 * HH, DD + HH, nullptr, nullptr);

        lstm_kernel<<<(BB * HH + 255) / 256, 256>>>(gates, lengths, t, h, c, hall);
    }

    zero_masked<<<BB * TT, 256>>>(lengths, out);

    // preds[active rows] = h_all @ W_fc^T + b_fc    [Mact, 1024] x [10000, 1024]
    gemm2<128, 128, 16, 8, 8, 3><<<dim3(20, 79), 256>>>(
        hall, HH, nullptr, W_fc, HH, nullptr,
        b_fc, nullptr, nullptr, 0,
        out, VV, BB * TT, VV, HH, rowidx, mact);
}

// round 4
// speedup vs baseline: 1.3375x; 1.1883x over previous
#include <cuda_runtime.h>
#include <cstdint>
#include <cstddef>

// Problem constants
#define BB 128
#define TT 20
#define VV 10000
#define EE 512
#define HH 1024
#define FF 196
#define DD 512

// ---------------------------------------------------------------------------
// Device scratch
// ---------------------------------------------------------------------------
__device__ float g_a_feat[(size_t)BB * FF * DD];
__device__ float g_x_emb[(size_t)BB * TT * EE];
__device__ float g_gemb[(size_t)BB * TT * 4 * HH];
__device__ float g_hall[(size_t)BB * TT * HH];
__device__ float g_h[BB * HH];
__device__ float g_c[BB * HH];
__device__ float g_z[BB * DD];
__device__ float g_z0[BB * DD];
__device__ float g_ah[BB * DD];
__device__ float g_gates[BB * 4 * HH];
__device__ int   g_rowidx[BB * TT];
__device__ int   g_mact[1];

__device__ __forceinline__ uint32_t f2tf32(float x) {
    uint32_t r;
    asm("cvt.rna.tf32.f32 %0, %1;" : "=r"(r) : "f"(x));
    return r;
}

__device__ __forceinline__ void mma_tf32(float c[4], const uint32_t a[4],
                                         const uint32_t b[2]) {
    asm volatile(
        "mma.sync.aligned.m16n8k8.row.col.f32.tf32.tf32.f32 "
        "{%0,%1,%2,%3}, {%4,%5,%6,%7}, {%8,%9}, {%0,%1,%2,%3};"
        : "+f"(c[0]), "+f"(c[1]), "+f"(c[2]), "+f"(c[3])
        : "r"(a[0]), "r"(a[1]), "r"(a[2]), "r"(a[3]), "r"(b[0]), "r"(b[1]));
}

// ---------------------------------------------------------------------------
// Tensor-core (mma.sync tf32) GEMM: C[M,N] = A[M,K] * B[N,K]^T
// CTA tile 128x128, BK=16, double-buffered smem, 8 warps of 64x32.
//   MODE 0: C = acc + bias[n] (+ bias2[n]).  M%128==0, N%128==0.
//   MODE 1: gates. A split [z(ld512) | h(ld1024)] at k=512;
//           B split [W_ih(ld1024) | W_hh(ld1024)]; C = acc + Cadd[gm*ldadd+gn].
//   MODE 3: fc over compacted rows: A row = rowidx[m], m < *mact; N-bounds.
// ---------------------------------------------------------------------------
#define SROW 20   // padded row length in floats (conflict-free fragment LDS)

template<int MODE>
__global__ void __launch_bounds__(256)
mma_gemm(const float* __restrict__ A, int lda,
         const float* __restrict__ A2,
         const float* __restrict__ Bm, int ldb,
         const float* __restrict__ B2,
         const float* __restrict__ bias, const float* __restrict__ bias2,
         const float* __restrict__ Cadd, int ldadd,
         float* __restrict__ C, int ldc,
         int M, int N, int K,
         const int* __restrict__ rowidx, const int* __restrict__ mact)
{
    __shared__ __align__(16) float As[2][128 * SROW];
    __shared__ __align__(16) float Bs[2][128 * SROW];
    __shared__ int sridx[128];

    const int tid = threadIdx.x;
    const int wid = tid >> 5;
    const int lane = tid & 31;
    const int g = lane >> 2;
    const int l = lane & 3;
    const int wm = (wid >> 2) * 64;   // warp row offset (2 warp-rows)
    const int wn = (wid & 3) * 32;    // warp col offset (4 warp-cols)
    const long m0 = (long)blockIdx.x * 128;
    const long n0 = (long)blockIdx.y * 128;

    int Mact = M;
    if (MODE == 3) {
        Mact = *mact;
        if (m0 >= Mact) return;
        if (tid < 128) {
            long gm = m0 + tid;
            sridx[tid] = (gm < Mact) ? rowidx[gm] : -1;
        }
        __syncthreads();
    }

    float acc[4][4][4];
#pragma unroll
    for (int i = 0; i < 4; i++)
#pragma unroll
        for (int j = 0; j < 4; j++)
#pragma unroll
            for (int k = 0; k < 4; k++) acc[i][j][k] = 0.f;

    float4 va[2], vb[2];
    auto ldgA = [&](int k0) {
#pragma unroll
        for (int i = 0; i < 2; i++) {
            int lin = tid + i * 256;
            int r = lin >> 2, kq = lin & 3;
            int gk = k0 + kq * 4;
            if (MODE == 1) {
                const float* p = (gk < 512)
                    ? (A  + (size_t)(m0 + r) * 512  + gk)
                    : (A2 + (size_t)(m0 + r) * 1024 + (gk - 512));
                va[i] = *(const float4*)p;
            } else if (MODE == 3) {
                int ar = sridx[r];
                va[i] = (ar >= 0) ? *(const float4*)(A + (size_t)ar * lda + gk)
                                  : make_float4(0.f, 0.f, 0.f, 0.f);
            } else {
                va[i] = *(const float4*)(A + (size_t)(m0 + r) * lda + gk);
            }
        }
    };
    auto ldgB = [&](int k0) {
#pragma unroll
        for (int i = 0; i < 2; i++) {
            int lin = tid + i * 256;
            int r = lin >> 2, kq = lin & 3;
            long gn = n0 + r;
            int gk = k0 + kq * 4;
            if (MODE == 1) {
                const float* p = (gk < 512)
                    ? (Bm + (size_t)gn * 1024 + gk)
                    : (B2 + (size_t)gn * 1024 + (gk - 512));
                vb[i] = *(const float4*)p;
            } else if (MODE == 3) {
                vb[i] = (gn < N) ? *(const float4*)(Bm + (size_t)gn * ldb + gk)
                                 : make_float4(0.f, 0.f, 0.f, 0.f);
            } else {
                vb[i] = *(const float4*)(Bm + (size_t)gn * ldb + gk);
            }
        }
    };
    auto stsAB = [&](int buf) {
#pragma unroll
        for (int i = 0; i < 2; i++) {
            int lin = tid + i * 256;
            int r = lin >> 2, kq = lin & 3;
            float4 ta, tb;
            ta.x = __uint_as_float(f2tf32(va[i].x));
            ta.y = __uint_as_float(f2tf32(va[i].y));
            ta.z = __uint_as_float(f2tf32(va[i].z));
            ta.w = __uint_as_float(f2tf32(va[i].w));
            tb.x = __uint_as_float(f2tf32(vb[i].x));
            tb.y = __uint_as_float(f2tf32(vb[i].y));
            tb.z = __uint_as_float(f2tf32(vb[i].z));
            tb.w = __uint_as_float(f2tf32(vb[i].w));
            *(float4*)&As[buf][r * SROW + kq * 4] = ta;
            *(float4*)&Bs[buf][r * SROW + kq * 4] = tb;
        }
    };

    const int nt_tiles = K >> 4;

    ldgA(0); ldgB(0);
    stsAB(0);
    __syncthreads();

    for (int kt = 0; kt < nt_tiles; kt++) {
        const int buf = kt & 1;
        const bool has_next = (kt + 1) < nt_tiles;
        if (has_next) { ldgA((kt + 1) * 16); ldgB((kt + 1) * 16); }

        const float* As_ = As[buf];
        const float* Bs_ = Bs[buf];
#pragma unroll
        for (int k8 = 0; k8 < 2; k8++) {
            const int kc = k8 * 8;
            uint32_t af[4][4];
#pragma unroll
            for (int mt = 0; mt < 4; mt++) {
                const float* p = As_ + (wm + mt * 16 + g) * SROW + kc + l;
                af[mt][0] = __float_as_uint(p[0]);
                af[mt][1] = __float_as_uint(p[8 * SROW]);
                af[mt][2] = __float_as_uint(p[4]);
                af[mt][3] = __float_as_uint(p[8 * SROW + 4]);
            }
            uint32_t bfr[4][2];
#pragma unroll
            for (int ntile = 0; ntile < 4; ntile++) {
                const float* q = Bs_ + (wn + ntile * 8 + g) * SROW + kc + l;
                bfr[ntile][0] = __float_as_uint(q[0]);
                bfr[ntile][1] = __float_as_uint(q[4]);
            }
#pragma unroll
            for (int mt = 0; mt < 4; mt++)
#pragma unroll
                for (int ntile = 0; ntile < 4; ntile++)
                    mma_tf32(acc[mt][ntile], af[mt], bfr[ntile]);
        }

        if (has_next) {
            stsAB(buf ^ 1);
            __syncthreads();
        }
    }

    // ---- epilogue ----
#pragma unroll
    for (int mt = 0; mt < 4; mt++) {
        const int r0l = wm + mt * 16 + g;
        const int r1l = r0l + 8;
        long gm0 = m0 + r0l, gm1 = m0 + r1l;
        bool ok0 = true, ok1 = true;
        float *crow0, *crow1;
        if (MODE == 3) {
            int a0 = sridx[r0l], a1 = sridx[r1l];
            ok0 = (a0 >= 0); ok1 = (a1 >= 0);
            crow0 = ok0 ? (C + (size_t)a0 * ldc) : nullptr;
            crow1 = ok1 ? (C + (size_t)a1 * ldc) : nullptr;
        } else {
            crow0 = C + (size_t)gm0 * ldc;
            crow1 = C + (size_t)gm1 * ldc;
        }
#pragma unroll
        for (int ntile = 0; ntile < 4; ntile++) {
            const int cn = wn + ntile * 8 + 2 * l;
            long gn = n0 + cn;
            if (MODE == 3 && gn >= N) continue;
            float2 v0 = make_float2(acc[mt][ntile][0], acc[mt][ntile][1]);
            float2 v1 = make_float2(acc[mt][ntile][2], acc[mt][ntile][3]);
            if (MODE == 0) {
                float bx = bias[gn], by = bias[gn + 1];
                if (bias2) { bx += bias2[gn]; by += bias2[gn + 1]; }
                v0.x += bx; v0.y += by; v1.x += bx; v1.y += by;
            } else if (MODE == 1) {
                const float* c0p = Cadd + (size_t)gm0 * ldadd + gn;
                const float* c1p = Cadd + (size_t)gm1 * ldadd + gn;
                v0.x += c0p[0]; v0.y += c0p[1];
                v1.x += c1p[0]; v1.y += c1p[1];
            } else {
                float bx = bias[gn], by = bias[gn + 1];
                v0.x += bx; v0.y += by; v1.x += bx; v1.y += by;
            }
            if (ok0) *(float2*)(crow0 + gn) = v0;
            if (ok1) *(float2*)(crow1 + gn) = v1;
        }
    }
}

// ---------------------------------------------------------------------------
// Support kernels
// ---------------------------------------------------------------------------
__global__ void compact_rows(const int* __restrict__ lengths,
                             int* __restrict__ rowidx, int* __restrict__ mact)
{
    __shared__ int off[BB + 1];
    __shared__ int cnts[BB];
    int b = threadIdx.x;
    int cnt = min(lengths[b] + 1, TT);
    cnts[b] = cnt;
    __syncthreads();
    if (b == 0) {
        int s = 0;
        for (int i = 0; i < BB; i++) { off[i] = s; s += cnts[i]; }
        off[BB] = s;
        *mact = s;
    }
    __syncthreads();
    int o = off[b];
    for (int j = 0; j < cnt; j++) rowidx[o + j] = b * TT + j;
}

__global__ void zero_masked(const int* __restrict__ lengths, float* __restrict__ out)
{
    int r = blockIdx.x;
    int b = r / TT, t = r % TT;
    if (lengths[b] >= t) return;
    float4 zz = make_float4(0.f, 0.f, 0.f, 0.f);
    float4* row = (float4*)(out + (size_t)r * VV);
    for (int i = threadIdx.x; i < VV / 4; i += blockDim.x) row[i] = zz;
}

__global__ void gather_kernel(const int* __restrict__ cap,
                              const float* __restrict__ emb,
                              float* __restrict__ xe)
{
    int r = blockIdx.x;
    int i = threadIdx.x;
    const float4* src = (const float4*)(emb + (size_t)cap[r] * EE);
    ((float4*)(xe + (size_t)r * EE))[i] = src[i];
}

__global__ void __launch_bounds__(256)
attn_fused(const float* __restrict__ a_feat,
           const float* __restrict__ ah,
           const float* __restrict__ w_a,
           const float* __restrict__ b_a,
           const float* __restrict__ feature,
           float* __restrict__ z)
{
    int b = blockIdx.x;
    int tid = threadIdx.x;
    int warp = tid >> 5, lane = tid & 31;
    __shared__ __align__(16) float s_ah[DD];
    __shared__ __align__(16) float s_w[DD];
    __shared__ float s_sc[FF];
    __shared__ float red[8];
    __shared__ float bmax, bsum;

    for (int i = tid; i < DD / 4; i += 256) {
        ((float4*)s_ah)[i] = ((const float4*)(ah + (size_t)b * DD))[i];
        ((float4*)s_w)[i]  = ((const float4*)w_a)[i];
    }
    __syncthreads();

    float ba = b_a[0];
    for (int f = warp; f < FF; f += 8) {
        const float4* af = (const float4*)(a_feat + ((size_t)b * FF + f) * DD);
        float s = 0.f;
#pragma unroll 4
        for (int k = lane; k < DD / 4; k += 32) {
            float4 a = af[k];
            float4 h4 = ((const float4*)s_ah)[k];
            float4 w4 = ((const float4*)s_w)[k];
            s += fmaxf(a.x + h4.x, 0.f) * w4.x
               + fmaxf(a.y + h4.y, 0.f) * w4.y
               + fmaxf(a.z + h4.z, 0.f) * w4.z
               + fmaxf(a.w + h4.w, 0.f) * w4.w;
        }
#pragma unroll
        for (int o = 16; o; o >>= 1) s += __shfl_down_sync(0xffffffffu, s, o);
        if (lane == 0) s_sc[f] = s + ba;
    }
    __syncthreads();

    float v = (tid < FF) ? s_sc[tid] : -3.0e38f;
    float m = v;
#pragma unroll
    for (int o = 16; o; o >>= 1) m = fmaxf(m, __shfl_xor_sync(0xffffffffu, m, o));
    if (lane == 0) red[warp] = m;
    __syncthreads();
    if (tid == 0) {
        float x = red[0];
        for (int w = 1; w < 8; w++) x = fmaxf(x, red[w]);
        bmax = x;
    }
    __syncthreads();
    float e = (tid < FF) ? expf(v - bmax) : 0.f;
    float s = e;
#pragma unroll
    for (int o = 16; o; o >>= 1) s += __shfl_xor_sync(0xffffffffu, s, o);
    if (lane == 0) red[warp] = s;
    __syncthreads();
    if (tid == 0) {
        float x = 0.f;
        for (int w = 0; w < 8; w++) x += red[w];
        bsum = x;
    }
    __syncthreads();
    if (tid < FF) s_sc[tid] = e / bsum;
    __syncthreads();

    const float* fp = feature + (size_t)b * FF * DD;
    for (int d = tid; d < DD; d += 256) {
        float s0 = 0.f, s1 = 0.f, s2 = 0.f, s3 = 0.f;
        for (int f = 0; f < FF; f += 4) {
            s0 += s_sc[f + 0] * fp[(size_t)(f + 0) * DD + d];
            s1 += s_sc[f + 1] * fp[(size_t)(f + 1) * DD + d];
            s2 += s_sc[f + 2] * fp[(size_t)(f + 2) * DD + d];
            s3 += s_sc[f + 3] * fp[(size_t)(f + 3) * DD + d];
        }
        z[(size_t)b * DD + d] = (s0 + s1) + (s2 + s3);
    }
}

__global__ void zmean_kernel(const float* __restrict__ feature,
                             float* __restrict__ z)
{
    int b = blockIdx.x;
    int d = blockIdx.y * 128 + threadIdx.x;
    const float* fp = feature + (size_t)b * FF * DD + d;
    float s0 = 0.f, s1 = 0.f, s2 = 0.f, s3 = 0.f;
    for (int f = 0; f < FF; f += 4) {
        s0 += fp[(size_t)(f + 0) * DD];
        s1 += fp[(size_t)(f + 1) * DD];
        s2 += fp[(size_t)(f + 2) * DD];
        s3 += fp[(size_t)(f + 3) * DD];
    }
    z[b * DD + d] = ((s0 + s1) + (s2 + s3)) * (1.0f / FF);
}

__device__ __forceinline__ float sigmoidf_(float x) { return 1.f / (1.f + expf(-x)); }

__global__ void lstm_kernel(const float* __restrict__ gates,
                            const int* __restrict__ lengths, int t,
                            float* __restrict__ h, float* __restrict__ c,
                            float* __restrict__ hall)
{
    int idx = blockIdx.x * blockDim.x + threadIdx.x;
    if (idx >= BB * HH) return;
    int b = idx >> 10;
    int hh = idx & (HH - 1);
    const float* g = gates + (size_t)b * 4 * HH;
    float ii = sigmoidf_(g[hh]);
    float ff = sigmoidf_(g[HH + hh]);
    float gg = tanhf(g[2 * HH + hh]);
    float oo = sigmoidf_(g[3 * HH + hh]);
    float cn = ff * c[idx] + ii * gg;
    float hn = oo * tanhf(cn);
    hall[((size_t)b * TT + t) * HH + hh] = hn;
    if (lengths[b] >= t) {
        h[idx] = hn;
        c[idx] = cn;
    }
}

// ---------------------------------------------------------------------------
// Host orchestration
// ---------------------------------------------------------------------------
extern "C" void kernel_launch(void* const* d_in, const int* in_sizes, int n_in,
                              void* d_out, int out_size)
{
    const float* feature = (const float*)d_in[0];
    const int*   captions = (const int*)d_in[1];
    const int*   lengths = (const int*)d_in[2];
    const float* emb    = (const float*)d_in[3];
    const float* W_ih   = (const float*)d_in[4];
    const float* b_ih   = (const float*)d_in[5];
    const float* W_hh   = (const float*)d_in[6];
    const float* b_hh   = (const float*)d_in[7];
    const float* W_fc   = (const float*)d_in[8];
    const float* b_fc   = (const float*)d_in[9];
    const float* W_h2a  = (const float*)d_in[10];
    const float* b_h2a  = (const float*)d_in[11];
    const float* W_f2a  = (const float*)d_in[12];
    const float* b_f2a  = (const float*)d_in[13];
    const float* W_a2a  = (const float*)d_in[14];
    const float* b_a2a  = (const float*)d_in[15];
    float* out = (float*)d_out;

    float *a_feat, *x_e, *gemb, *hall, *h, *c, *z, *z0, *ah, *gates;
    int *rowidx, *mact;
    cudaGetSymbolAddress((void**)&a_feat, g_a_feat);
    cudaGetSymbolAddress((void**)&x_e,    g_x_emb);
    cudaGetSymbolAddress((void**)&gemb,   g_gemb);
    cudaGetSymbolAddress((void**)&hall,   g_hall);
    cudaGetSymbolAddress((void**)&h,      g_h);
    cudaGetSymbolAddress((void**)&c,      g_c);
    cudaGetSymbolAddress((void**)&z,      g_z);
    cudaGetSymbolAddress((void**)&z0,     g_z0);
    cudaGetSymbolAddress((void**)&ah,     g_ah);
    cudaGetSymbolAddress((void**)&gates,  g_gates);
    cudaGetSymbolAddress((void**)&rowidx, g_rowidx);
    cudaGetSymbolAddress((void**)&mact,   g_mact);

    cudaMemsetAsync(h, 0, (size_t)BB * HH * sizeof(float));
    cudaMemsetAsync(c, 0, (size_t)BB * HH * sizeof(float));

    gather_kernel<<<BB * TT, 128>>>(captions, emb, x_e);
    compact_rows<<<1, BB>>>(lengths, rowidx, mact);

    // a_feat = feature @ W_f2a^T + b_f2a      [25088, 512] x [512, 512]
    mma_gemm<0><<<dim3(196, 4), 256>>>(
        feature, DD, nullptr, W_f2a, DD, nullptr,
        b_f2a, nullptr, nullptr, 0,
        a_feat, DD, BB * FF, DD, DD, nullptr, nullptr);

    // g_emb = x_emb @ W_ih[:, D:]^T + b_ih + b_hh   [2560, 512] x [4096, 512]
    mma_gemm<0><<<dim3(20, 32), 256>>>(
        x_e, EE, nullptr, W_ih + DD, DD + EE, nullptr,
        b_ih, b_hh, nullptr, 0,
        gemb, 4 * HH, BB * TT, 4 * HH, EE, nullptr, nullptr);

    zmean_kernel<<<dim3(BB, DD / 128), 128>>>(feature, z0);

    for (int t = 0; t < TT; t++) {
        const float* zptr = z0;
        if (t > 0) {
            // a_h = h @ W_h2a^T + b_h2a     [128, 1024] x [512, 1024]
            mma_gemm<0><<<dim3(1, 4), 256>>>(
                h, HH, nullptr, W_h2a, HH, nullptr,
                b_h2a, nullptr, nullptr, 0,
                ah, DD, BB, DD, HH, nullptr, nullptr);

            attn_fused<<<BB, 256>>>(a_feat, ah, W_a2a, b_a2a, feature, z);
            zptr = z;
        }

        // gates = g_emb[:, t, :] + [z | h] @ [W_ih[:, :D] | W_hh]^T
        mma_gemm<1><<<dim3(1, 32), 256>>>(
            zptr, 0, h, W_ih, 0, W_hh,
            nullptr, nullptr, gemb + (size_t)t * 4 * HH, TT * 4 * HH,
            gates, 4 * HH, BB, 4 * HH, DD + HH, nullptr, nullptr);

        lstm_kernel<<<(BB * HH + 255) / 256, 256>>>(gates, lengths, t, h, c, hall);
    }

    zero_masked<<<BB * TT, 256>>>(lengths, out);

    // preds[active rows] = h_all @ W_fc^T + b_fc    [Mact, 1024] x [10000, 1024]
    mma_gemm<3><<<dim3(20, 79), 256>>>(
        hall, HH, nullptr, W_fc, HH, nullptr,
        b_fc, nullptr, nullptr, 0,
        out, VV, BB * TT, VV, HH, rowidx, mact);
}

// round 5
// speedup vs baseline: 2.1835x; 1.6325x over previous
#include <cuda_runtime.h>
#include <cstdint>
#include <cstddef>

// Problem constants
#define BB 128
#define TT 20
#define VV 10000
#define EE 512
#define HH 1024
#define FF 196
#define DD 512

// ---------------------------------------------------------------------------
// Device scratch
// ---------------------------------------------------------------------------
__device__ float g_a_feat[(size_t)BB * FF * DD];
__device__ float g_x_emb[(size_t)BB * TT * EE];
__device__ float g_gemb[(size_t)BB * TT * 4 * HH];
__device__ float g_hall[(size_t)BB * TT * HH];
__device__ float g_h[BB * HH];
__device__ float g_c[BB * HH];
__device__ float g_z[BB * DD];
__device__ float g_z0[BB * DD];
__device__ float g_ahp[4 * BB * DD];          // split-K partials for a_h
__device__ float g_gatesp[3 * BB * 4 * HH];   // split-K partials for gates
__device__ int   g_rowidx[BB * TT];
__device__ int   g_mact[1];

__device__ __forceinline__ uint32_t f2tf32(float x) {
    uint32_t r;
    asm("cvt.rna.tf32.f32 %0, %1;" : "=r"(r) : "f"(x));
    return r;
}

__device__ __forceinline__ void mma_tf32(float c[4], const uint32_t a[4],
                                         const uint32_t b[2]) {
    asm volatile(
        "mma.sync.aligned.m16n8k8.row.col.f32.tf32.tf32.f32 "
        "{%0,%1,%2,%3}, {%4,%5,%6,%7}, {%8,%9}, {%0,%1,%2,%3};"
        : "+f"(c[0]), "+f"(c[1]), "+f"(c[2]), "+f"(c[3])
        : "r"(a[0]), "r"(a[1]), "r"(a[2]), "r"(a[3]), "r"(b[0]), "r"(b[1]));
}

// ---------------------------------------------------------------------------
// Tensor-core (mma.sync tf32) GEMM: C[M,N] = A[M,K] * B[N,K]^T
// CTA tile 128x128, BK=16, double-buffered smem, 8 warps of 64x32.
//   MODE 0: C = acc + bias[n] (+ bias2[n]).  M%128==0, N%128==0.
//   MODE 3: fc over compacted rows: A row = rowidx[m], m < *mact; N-bounds.
//   MODE 4: gates split-K partial. blockIdx.z = zi in {0,1,2}, K = 512 chunk.
//           zi 0: A = z (ld 512), B = W_ih (ld 1024) cols 0-511
//           zi 1: A = h cols 0-511 (ld 1024), B = W_hh cols 0-511
//           zi 2: A = h cols 512-1023, B = W_hh cols 512-1023
//           raw partial -> C + zi*M*ldc
//   MODE 5: plain split-K partial: k offset = blockIdx.z*K,
//           raw partial -> C + blockIdx.z*M*ldc
// ---------------------------------------------------------------------------
#define SROW 20   // padded row length in floats (conflict-free fragment LDS)

template<int MODE>
__global__ void __launch_bounds__(256)
mma_gemm(const float* __restrict__ A, int lda,
         const float* __restrict__ A2,
         const float* __restrict__ Bm, int ldb,
         const float* __restrict__ B2,
         const float* __restrict__ bias, const float* __restrict__ bias2,
         float* __restrict__ C, int ldc,
         int M, int N, int K,
         const int* __restrict__ rowidx, const int* __restrict__ mact)
{
    __shared__ __align__(16) float As[2][128 * SROW];
    __shared__ __align__(16) float Bs[2][128 * SROW];
    __shared__ int sridx[128];

    const int tid = threadIdx.x;
    const int wid = tid >> 5;
    const int lane = tid & 31;
    const int g = lane >> 2;
    const int l = lane & 3;
    const int wm = (wid >> 2) * 64;
    const int wn = (wid & 3) * 32;
    const long m0 = (long)blockIdx.x * 128;
    const long n0 = (long)blockIdx.y * 128;
    const int zi = blockIdx.z;
    const int kofs = (MODE == 5) ? zi * K : 0;

    int Mact = M;
    if (MODE == 3) {
        Mact = *mact;
        if (m0 >= Mact) return;
        if (tid < 128) {
            long gm = m0 + tid;
            sridx[tid] = (gm < Mact) ? rowidx[gm] : -1;
        }
        __syncthreads();
    }

    float acc[4][4][4];
#pragma unroll
    for (int i = 0; i < 4; i++)
#pragma unroll
        for (int j = 0; j < 4; j++)
#pragma unroll
            for (int k = 0; k < 4; k++) acc[i][j][k] = 0.f;

    float4 va[2], vb[2];
    auto ldgA = [&](int k0) {
#pragma unroll
        for (int i = 0; i < 2; i++) {
            int lin = tid + i * 256;
            int r = lin >> 2, kq = lin & 3;
            int gk = k0 + kq * 4;
            if (MODE == 4) {
                const float* p = (zi == 0)
                    ? (A  + (size_t)(m0 + r) * 512  + gk)
                    : (A2 + (size_t)(m0 + r) * 1024 + (zi - 1) * 512 + gk);
                va[i] = *(const float4*)p;
            } else if (MODE == 5) {
                va[i] = *(const float4*)(A + (size_t)(m0 + r) * lda + kofs + gk);
            } else if (MODE == 3) {
                int ar = sridx[r];
                va[i] = (ar >= 0) ? *(const float4*)(A + (size_t)ar * lda + gk)
                                  : make_float4(0.f, 0.f, 0.f, 0.f);
            } else {
                va[i] = *(const float4*)(A + (size_t)(m0 + r) * lda + gk);
            }
        }
    };
    auto ldgB = [&](int k0) {
#pragma unroll
        for (int i = 0; i < 2; i++) {
            int lin = tid + i * 256;
            int r = lin >> 2, kq = lin & 3;
            long gn = n0 + r;
            int gk = k0 + kq * 4;
            if (MODE == 4) {
                const float* p = (zi == 0)
                    ? (Bm + (size_t)gn * 1024 + gk)
                    : (B2 + (size_t)gn * 1024 + (zi - 1) * 512 + gk);
                vb[i] = *(const float4*)p;
            } else if (MODE == 5) {
                vb[i] = *(const float4*)(Bm + (size_t)gn * ldb + kofs + gk);
            } else if (MODE == 3) {
                vb[i] = (gn < N) ? *(const float4*)(Bm + (size_t)gn * ldb + gk)
                                 : make_float4(0.f, 0.f, 0.f, 0.f);
            } else {
                vb[i] = *(const float4*)(Bm + (size_t)gn * ldb + gk);
            }
        }
    };
    auto stsAB = [&](int buf) {
#pragma unroll
        for (int i = 0; i < 2; i++) {
            int lin = tid + i * 256;
            int r = lin >> 2, kq = lin & 3;
            float4 ta, tb;
            ta.x = __uint_as_float(f2tf32(va[i].x));
            ta.y = __uint_as_float(f2tf32(va[i].y));
            ta.z = __uint_as_float(f2tf32(va[i].z));
            ta.w = __uint_as_float(f2tf32(va[i].w));
            tb.x = __uint_as_float(f2tf32(vb[i].x));
            tb.y = __uint_as_float(f2tf32(vb[i].y));
            tb.z = __uint_as_float(f2tf32(vb[i].z));
            tb.w = __uint_as_float(f2tf32(vb[i].w));
            *(float4*)&As[buf][r * SROW + kq * 4] = ta;
            *(float4*)&Bs[buf][r * SROW + kq * 4] = tb;
        }
    };

    const int nt_tiles = K >> 4;

    ldgA(0); ldgB(0);
    stsAB(0);
    __syncthreads();

    for (int kt = 0; kt < nt_tiles; kt++) {
        const int buf = kt & 1;
        const bool has_next = (kt + 1) < nt_tiles;
        if (has_next) { ldgA((kt + 1) * 16); ldgB((kt + 1) * 16); }

        const float* As_ = As[buf];
        const float* Bs_ = Bs[buf];
#pragma unroll
        for (int k8 = 0; k8 < 2; k8++) {
            const int kc = k8 * 8;
            uint32_t af[4][4];
#pragma unroll
            for (int mt = 0; mt < 4; mt++) {
                const float* p = As_ + (wm + mt * 16 + g) * SROW + kc + l;
                af[mt][0] = __float_as_uint(p[0]);
                af[mt][1] = __float_as_uint(p[8 * SROW]);
                af[mt][2] = __float_as_uint(p[4]);
                af[mt][3] = __float_as_uint(p[8 * SROW + 4]);
            }
            uint32_t bfr[4][2];
#pragma unroll
            for (int ntile = 0; ntile < 4; ntile++) {
                const float* q = Bs_ + (wn + ntile * 8 + g) * SROW + kc + l;
                bfr[ntile][0] = __float_as_uint(q[0]);
                bfr[ntile][1] = __float_as_uint(q[4]);
            }
#pragma unroll
            for (int mt = 0; mt < 4; mt++)
#pragma unroll
                for (int ntile = 0; ntile < 4; ntile++)
                    mma_tf32(acc[mt][ntile], af[mt], bfr[ntile]);
        }

        if (has_next) {
            stsAB(buf ^ 1);
            __syncthreads();
        }
    }

    // ---- epilogue ----
    float* Cp = C;
    if (MODE == 4 || MODE == 5) Cp = C + (size_t)zi * M * ldc;

#pragma unroll
    for (int mt = 0; mt < 4; mt++) {
        const int r0l = wm + mt * 16 + g;
        const int r1l = r0l + 8;
        long gm0 = m0 + r0l, gm1 = m0 + r1l;
        bool ok0 = true, ok1 = true;
        float *crow0, *crow1;
        if (MODE == 3) {
            int a0 = sridx[r0l], a1 = sridx[r1l];
            ok0 = (a0 >= 0); ok1 = (a1 >= 0);
            crow0 = ok0 ? (Cp + (size_t)a0 * ldc) : nullptr;
            crow1 = ok1 ? (Cp + (size_t)a1 * ldc) : nullptr;
        } else {
            crow0 = Cp + (size_t)gm0 * ldc;
            crow1 = Cp + (size_t)gm1 * ldc;
        }
#pragma unroll
        for (int ntile = 0; ntile < 4; ntile++) {
            const int cn = wn + ntile * 8 + 2 * l;
            long gn = n0 + cn;
            if (MODE == 3 && gn >= N) continue;
            float2 v0 = make_float2(acc[mt][ntile][0], acc[mt][ntile][1]);
            float2 v1 = make_float2(acc[mt][ntile][2], acc[mt][ntile][3]);
            if (MODE == 0 || MODE == 3) {
                float bx = bias[gn], by = bias[gn + 1];
                if (MODE == 0 && bias2) { bx += bias2[gn]; by += bias2[gn + 1]; }
                v0.x += bx; v0.y += by; v1.x += bx; v1.y += by;
            }
            if (ok0) *(float2*)(crow0 + gn) = v0;
            if (ok1) *(float2*)(crow1 + gn) = v1;
        }
    }
}

// ---------------------------------------------------------------------------
// Support kernels
// ---------------------------------------------------------------------------
__global__ void compact_rows(const int* __restrict__ lengths,
                             int* __restrict__ rowidx, int* __restrict__ mact)
{
    __shared__ int off[BB + 1];
    __shared__ int cnts[BB];
    int b = threadIdx.x;
    int cnt = min(lengths[b] + 1, TT);
    cnts[b] = cnt;
    __syncthreads();
    if (b == 0) {
        int s = 0;
        for (int i = 0; i < BB; i++) { off[i] = s; s += cnts[i]; }
        off[BB] = s;
        *mact = s;
    }
    __syncthreads();
    int o = off[b];
    for (int j = 0; j < cnt; j++) rowidx[o + j] = b * TT + j;
}

__global__ void zero_masked(const int* __restrict__ lengths, float* __restrict__ out)
{
    int r = blockIdx.x;
    int b = r / TT, t = r % TT;
    if (lengths[b] >= t) return;
    float4 zz = make_float4(0.f, 0.f, 0.f, 0.f);
    float4* row = (float4*)(out + (size_t)r * VV);
    for (int i = threadIdx.x; i < VV / 4; i += blockDim.x) row[i] = zz;
}

__global__ void gather_kernel(const int* __restrict__ cap,
                              const float* __restrict__ emb,
                              float* __restrict__ xe)
{
    int r = blockIdx.x;
    int i = threadIdx.x;
    const float4* src = (const float4*)(emb + (size_t)cap[r] * EE);
    ((float4*)(xe + (size_t)r * EE))[i] = src[i];
}

// ---------------------------------------------------------------------------
// Fused attention (reads split-K a_h partials + b_h2a)
// ---------------------------------------------------------------------------
__global__ void __launch_bounds__(256)
attn_fused(const float* __restrict__ a_feat,
           const float* __restrict__ ahp,
           const float* __restrict__ b_h2a,
           const float* __restrict__ w_a,
           const float* __restrict__ b_a,
           const float* __restrict__ feature,
           float* __restrict__ z)
{
    int b = blockIdx.x;
    int tid = threadIdx.x;
    int warp = tid >> 5, lane = tid & 31;
    __shared__ __align__(16) float s_ah[DD];
    __shared__ __align__(16) float s_w[DD];
    __shared__ float s_sc[FF];
    __shared__ float red[8];
    __shared__ float bmax, bsum;

    for (int i = tid; i < DD / 4; i += 256) {
        float4 v = ((const float4*)b_h2a)[i];
#pragma unroll
        for (int zp = 0; zp < 4; zp++) {
            float4 p = ((const float4*)(ahp + ((size_t)zp * BB + b) * DD))[i];
            v.x += p.x; v.y += p.y; v.z += p.z; v.w += p.w;
        }
        ((float4*)s_ah)[i] = v;
        ((float4*)s_w)[i]  = ((const float4*)w_a)[i];
    }
    __syncthreads();

    float ba = b_a[0];
    for (int f = warp; f < FF; f += 8) {
        const float4* af = (const float4*)(a_feat + ((size_t)b * FF + f) * DD);
        float s = 0.f;
#pragma unroll 4
        for (int k = lane; k < DD / 4; k += 32) {
            float4 a = af[k];
            float4 h4 = ((const float4*)s_ah)[k];
            float4 w4 = ((const float4*)s_w)[k];
            s += fmaxf(a.x + h4.x, 0.f) * w4.x
               + fmaxf(a.y + h4.y, 0.f) * w4.y
               + fmaxf(a.z + h4.z, 0.f) * w4.z
               + fmaxf(a.w + h4.w, 0.f) * w4.w;
        }
#pragma unroll
        for (int o = 16; o; o >>= 1) s += __shfl_down_sync(0xffffffffu, s, o);
        if (lane == 0) s_sc[f] = s + ba;
    }
    __syncthreads();

    float v = (tid < FF) ? s_sc[tid] : -3.0e38f;
    float m = v;
#pragma unroll
    for (int o = 16; o; o >>= 1) m = fmaxf(m, __shfl_xor_sync(0xffffffffu, m, o));
    if (lane == 0) red[warp] = m;
    __syncthreads();
    if (tid == 0) {
        float x = red[0];
        for (int w = 1; w < 8; w++) x = fmaxf(x, red[w]);
        bmax = x;
    }
    __syncthreads();
    float e = (tid < FF) ? expf(v - bmax) : 0.f;
    float s = e;
#pragma unroll
    for (int o = 16; o; o >>= 1) s += __shfl_xor_sync(0xffffffffu, s, o);
    if (lane == 0) red[warp] = s;
    __syncthreads();
    if (tid == 0) {
        float x = 0.f;
        for (int w = 0; w < 8; w++) x += red[w];
        bsum = x;
    }
    __syncthreads();
    if (tid < FF) s_sc[tid] = e / bsum;
    __syncthreads();

    const float* fp = feature + (size_t)b * FF * DD;
    for (int d = tid; d < DD; d += 256) {
        float s0 = 0.f, s1 = 0.f, s2 = 0.f, s3 = 0.f;
        for (int f = 0; f < FF; f += 4) {
            s0 += s_sc[f + 0] * fp[(size_t)(f + 0) * DD + d];
            s1 += s_sc[f + 1] * fp[(size_t)(f + 1) * DD + d];
            s2 += s_sc[f + 2] * fp[(size_t)(f + 2) * DD + d];
            s3 += s_sc[f + 3] * fp[(size_t)(f + 3) * DD + d];
        }
        z[(size_t)b * DD + d] = (s0 + s1) + (s2 + s3);
    }
}

__global__ void zmean_kernel(const float* __restrict__ feature,
                             float* __restrict__ z)
{
    int b = blockIdx.x;
    int d = blockIdx.y * 128 + threadIdx.x;
    const float* fp = feature + (size_t)b * FF * DD + d;
    float s0 = 0.f, s1 = 0.f, s2 = 0.f, s3 = 0.f;
    for (int f = 0; f < FF; f += 4) {
        s0 += fp[(size_t)(f + 0) * DD];
        s1 += fp[(size_t)(f + 1) * DD];
        s2 += fp[(size_t)(f + 2) * DD];
        s3 += fp[(size_t)(f + 3) * DD];
    }
    z[b * DD + d] = ((s0 + s1) + (s2 + s3)) * (1.0f / FF);
}

__device__ __forceinline__ float sigmoidf_(float x) { return 1.f / (1.f + expf(-x)); }

// LSTM pointwise: sums 3 split-K gate partials + precomputed gemb slice.
__global__ void lstm_kernel(const float* __restrict__ gp,
                            const float* __restrict__ gemb,
                            const int* __restrict__ lengths, int t,
                            float* __restrict__ h, float* __restrict__ c,
                            float* __restrict__ hall)
{
    int idx = blockIdx.x * blockDim.x + threadIdx.x;
    if (idx >= BB * HH) return;
    int b = idx >> 10;
    int hh = idx & (HH - 1);
    const size_t S = (size_t)BB * 4 * HH;
    const size_t base = (size_t)b * 4 * HH;
    const float* g0 = gp + base;
    const float* g1 = gp + S + base;
    const float* g2 = gp + 2 * S + base;
    const float* ge = gemb + ((size_t)b * TT + t) * 4 * HH;

    float vi = g0[hh] + g1[hh] + g2[hh] + ge[hh];
    float vf = g0[HH + hh] + g1[HH + hh] + g2[HH + hh] + ge[HH + hh];
    float vg = g0[2 * HH + hh] + g1[2 * HH + hh] + g2[2 * HH + hh] + ge[2 * HH + hh];
    float vo = g0[3 * HH + hh] + g1[3 * HH + hh] + g2[3 * HH + hh] + ge[3 * HH + hh];

    float ii = sigmoidf_(vi);
    float ff = sigmoidf_(vf);
    float gg = tanhf(vg);
    float oo = sigmoidf_(vo);
    float cn = ff * c[idx] + ii * gg;
    float hn = oo * tanhf(cn);
    hall[((size_t)b * TT + t) * HH + hh] = hn;
    if (lengths[b] >= t) {
        h[idx] = hn;
        c[idx] = cn;
    }
}

// ---------------------------------------------------------------------------
// Host orchestration
// ---------------------------------------------------------------------------
extern "C" void kernel_launch(void* const* d_in, const int* in_sizes, int n_in,
                              void* d_out, int out_size)
{
    const float* feature = (const float*)d_in[0];
    const int*   captions = (const int*)d_in[1];
    const int*   lengths = (const int*)d_in[2];
    const float* emb    = (const float*)d_in[3];
    const float* W_ih   = (const float*)d_in[4];
    const float* b_ih   = (const float*)d_in[5];
    const float* W_hh   = (const float*)d_in[6];
    const float* b_hh   = (const float*)d_in[7];
    const float* W_fc   = (const float*)d_in[8];
    const float* b_fc   = (const float*)d_in[9];
    const float* W_h2a  = (const float*)d_in[10];
    const float* b_h2a  = (const float*)d_in[11];
    const float* W_f2a  = (const float*)d_in[12];
    const float* b_f2a  = (const float*)d_in[13];
    const float* W_a2a  = (const float*)d_in[14];
    const float* b_a2a  = (const float*)d_in[15];
    float* out = (float*)d_out;

    float *a_feat, *x_e, *gemb, *hall, *h, *c, *z, *z0, *ahp, *gatesp;
    int *rowidx, *mact;
    cudaGetSymbolAddress((void**)&a_feat, g_a_feat);
    cudaGetSymbolAddress((void**)&x_e,    g_x_emb);
    cudaGetSymbolAddress((void**)&gemb,   g_gemb);
    cudaGetSymbolAddress((void**)&hall,   g_hall);
    cudaGetSymbolAddress((void**)&h,      g_h);
    cudaGetSymbolAddress((void**)&c,      g_c);
    cudaGetSymbolAddress((void**)&z,      g_z);
    cudaGetSymbolAddress((void**)&z0,     g_z0);
    cudaGetSymbolAddress((void**)&ahp,    g_ahp);
    cudaGetSymbolAddress((void**)&gatesp, g_gatesp);
    cudaGetSymbolAddress((void**)&rowidx, g_rowidx);
    cudaGetSymbolAddress((void**)&mact,   g_mact);

    cudaMemsetAsync(h, 0, (size_t)BB * HH * sizeof(float));
    cudaMemsetAsync(c, 0, (size_t)BB * HH * sizeof(float));

    gather_kernel<<<BB * TT, 128>>>(captions, emb, x_e);
    compact_rows<<<1, BB>>>(lengths, rowidx, mact);

    // a_feat = feature @ W_f2a^T + b_f2a      [25088, 512] x [512, 512]
    mma_gemm<0><<<dim3(196, 4), 256>>>(
        feature, DD, nullptr, W_f2a, DD, nullptr,
        b_f2a, nullptr,
        a_feat, DD, BB * FF, DD, DD, nullptr, nullptr);

    // g_emb = x_emb @ W_ih[:, D:]^T + b_ih + b_hh   [2560, 512] x [4096, 512]
    mma_gemm<0><<<dim3(20, 32), 256>>>(
        x_e, EE, nullptr, W_ih + DD, DD + EE, nullptr,
        b_ih, b_hh,
        gemb, 4 * HH, BB * TT, 4 * HH, EE, nullptr, nullptr);

    zmean_kernel<<<dim3(BB, DD / 128), 128>>>(feature, z0);

    for (int t = 0; t < TT; t++) {
        const float* zptr = z0;
        if (t > 0) {
            // a_h partials: h @ W_h2a^T, split-K=4 (chunks of 256)
            mma_gemm<5><<<dim3(1, 4, 4), 256>>>(
                h, HH, nullptr, W_h2a, HH, nullptr,
                nullptr, nullptr,
                ahp, DD, BB, DD, 256, nullptr, nullptr);

            attn_fused<<<BB, 256>>>(a_feat, ahp, b_h2a, W_a2a, b_a2a, feature, z);
            zptr = z;
        }

        // gates partials: [z|h] @ [W_ih[:, :D]|W_hh]^T, split-K=3 (512 each)
        mma_gemm<4><<<dim3(1, 32, 3), 256>>>(
            zptr, 0, h, W_ih, 0, W_hh,
            nullptr, nullptr,
            gatesp, 4 * HH, BB, 4 * HH, 512, nullptr, nullptr);

        lstm_kernel<<<(BB * HH + 255) / 256, 256>>>(gatesp, gemb, lengths, t,
                                                    h, c, hall);
    }

    zero_masked<<<BB * TT, 256>>>(lengths, out);

    // preds[active rows] = h_all @ W_fc^T + b_fc    [Mact, 1024] x [10000, 1024]
    mma_gemm<3><<<dim3(20, 79), 256>>>(
        hall, HH, nullptr, W_fc, HH, nullptr,
        b_fc, nullptr,
        out, VV, BB * TT, VV, HH, rowidx, mact);
}

// round 6
// speedup vs baseline: 2.2533x; 1.0320x over previous
#include <cuda_runtime.h>
#include <cstdint>
#include <cstddef>

// Problem constants
#define BB 128
#define TT 20
#define VV 10000
#define EE 512
#define HH 1024
#define FF 196
#define DD 512

// ---------------------------------------------------------------------------
// Device scratch
// ---------------------------------------------------------------------------
__device__ float g_a_feat[(size_t)BB * FF * DD];
__device__ float g_x_emb[(size_t)BB * TT * EE];
__device__ float g_gemb[(size_t)BB * TT * 4 * HH];
__device__ float g_hall[(size_t)BB * TT * HH];
__device__ float g_h[BB * HH];
__device__ float g_c[BB * HH];
__device__ float g_z[BB * DD];
__device__ float g_z0[BB * DD];
__device__ float g_ahp[4 * BB * DD];          // split-K partials for a_h
__device__ float g_gatesp[3 * BB * 4 * HH];   // split-K partials for gates
__device__ int   g_rowidx[BB * TT];
__device__ int   g_mact[1];

__device__ __forceinline__ uint32_t f2tf32(float x) {
    uint32_t r;
    asm("cvt.rna.tf32.f32 %0, %1;" : "=r"(r) : "f"(x));
    return r;
}

__device__ __forceinline__ void mma_tf32(float c[4], const uint32_t a[4],
                                         const uint32_t b[2]) {
    asm volatile(
        "mma.sync.aligned.m16n8k8.row.col.f32.tf32.tf32.f32 "
        "{%0,%1,%2,%3}, {%4,%5,%6,%7}, {%8,%9}, {%0,%1,%2,%3};"
        : "+f"(c[0]), "+f"(c[1]), "+f"(c[2]), "+f"(c[3])
        : "r"(a[0]), "r"(a[1]), "r"(a[2]), "r"(a[3]), "r"(b[0]), "r"(b[1]));
}

// ---------------------------------------------------------------------------
// Tensor-core (mma.sync tf32) GEMM: C[M,N] = A[M,K] * B[N,K]^T
// CTA tile 128x128, BK=16, double-buffered smem, 8 warps of 64x32.
//   MODE 0: C = acc + bias[n] (+ bias2[n]).  M%128==0, N%128==0.
//   MODE 3: fc over compacted rows: A row = rowidx[m], m < *mact; N-bounds.
//   MODE 4: gates split-K partial. zi = zbase + blockIdx.z in {0,1,2}, K=512.
//           zi 0: A = z (ld 512), B = W_ih (ld 1024) cols 0-511
//           zi 1: A = h cols 0-511 (ld 1024), B = W_hh cols 0-511
//           zi 2: A = h cols 512-1023, B = W_hh cols 512-1023
//           raw partial -> C + zi*M*ldc
//   MODE 5: plain split-K partial: k offset = zi*K, raw partial -> C + zi*M*ldc
// ---------------------------------------------------------------------------
#define SROW 20   // padded row length in floats (conflict-free fragment LDS)

template<int MODE>
__global__ void __launch_bounds__(256, 2)
mma_gemm(const float* __restrict__ A, int lda,
         const float* __restrict__ A2,
         const float* __restrict__ Bm, int ldb,
         const float* __restrict__ B2,
         const float* __restrict__ bias, const float* __restrict__ bias2,
         float* __restrict__ C, int ldc,
         int M, int N, int K, int zbase,
         const int* __restrict__ rowidx, const int* __restrict__ mact)
{
    __shared__ __align__(16) float As[2][128 * SROW];
    __shared__ __align__(16) float Bs[2][128 * SROW];
    __shared__ int sridx[128];

    const int tid = threadIdx.x;
    const int wid = tid >> 5;
    const int lane = tid & 31;
    const int g = lane >> 2;
    const int l = lane & 3;
    const int wm = (wid >> 2) * 64;
    const int wn = (wid & 3) * 32;
    const long m0 = (long)blockIdx.x * 128;
    const long n0 = (long)blockIdx.y * 128;
    const int zi = zbase + blockIdx.z;
    const int kofs = (MODE == 5) ? zi * K : 0;

    int Mact = M;
    if (MODE == 3) {
        Mact = *mact;
        if (m0 >= Mact) return;
        if (tid < 128) {
            long gm = m0 + tid;
            sridx[tid] = (gm < Mact) ? rowidx[gm] : -1;
        }
        __syncthreads();
    }

    float acc[4][4][4];
#pragma unroll
    for (int i = 0; i < 4; i++)
#pragma unroll
        for (int j = 0; j < 4; j++)
#pragma unroll
            for (int k = 0; k < 4; k++) acc[i][j][k] = 0.f;

    float4 va[2], vb[2];
    auto ldgA = [&](int k0) {
#pragma unroll
        for (int i = 0; i < 2; i++) {
            int lin = tid + i * 256;
            int r = lin >> 2, kq = lin & 3;
            int gk = k0 + kq * 4;
            if (MODE == 4) {
                const float* p = (zi == 0)
                    ? (A  + (size_t)(m0 + r) * 512  + gk)
                    : (A2 + (size_t)(m0 + r) * 1024 + (zi - 1) * 512 + gk);
                va[i] = *(const float4*)p;
            } else if (MODE == 5) {
                va[i] = *(const float4*)(A + (size_t)(m0 + r) * lda + kofs + gk);
            } else if (MODE == 3) {
                int ar = sridx[r];
                va[i] = (ar >= 0) ? *(const float4*)(A + (size_t)ar * lda + gk)
                                  : make_float4(0.f, 0.f, 0.f, 0.f);
            } else {
                va[i] = *(const float4*)(A + (size_t)(m0 + r) * lda + gk);
            }
        }
    };
    auto ldgB = [&](int k0) {
#pragma unroll
        for (int i = 0; i < 2; i++) {
            int lin = tid + i * 256;
            int r = lin >> 2, kq = lin & 3;
            long gn = n0 + r;
            int gk = k0 + kq * 4;
            if (MODE == 4) {
                const float* p = (zi == 0)
                    ? (Bm + (size_t)gn * 1024 + gk)
                    : (B2 + (size_t)gn * 1024 + (zi - 1) * 512 + gk);
                vb[i] = *(const float4*)p;
            } else if (MODE == 5) {
                vb[i] = *(const float4*)(Bm + (size_t)gn * ldb + kofs + gk);
            } else if (MODE == 3) {
                vb[i] = (gn < N) ? *(const float4*)(Bm + (size_t)gn * ldb + gk)
                                 : make_float4(0.f, 0.f, 0.f, 0.f);
            } else {
                vb[i] = *(const float4*)(Bm + (size_t)gn * ldb + gk);
            }
        }
    };
    auto stsAB = [&](int buf) {
#pragma unroll
        for (int i = 0; i < 2; i++) {
            int lin = tid + i * 256;
            int r = lin >> 2, kq = lin & 3;
            float4 ta, tb;
            ta.x = __uint_as_float(f2tf32(va[i].x));
            ta.y = __uint_as_float(f2tf32(va[i].y));
            ta.z = __uint_as_float(f2tf32(va[i].z));
            ta.w = __uint_as_float(f2tf32(va[i].w));
            tb.x = __uint_as_float(f2tf32(vb[i].x));
            tb.y = __uint_as_float(f2tf32(vb[i].y));
            tb.z = __uint_as_float(f2tf32(vb[i].z));
            tb.w = __uint_as_float(f2tf32(vb[i].w));
            *(float4*)&As[buf][r * SROW + kq * 4] = ta;
            *(float4*)&Bs[buf][r * SROW + kq * 4] = tb;
        }
    };

    const int nt_tiles = K >> 4;

    ldgA(0); ldgB(0);
    stsAB(0);
    __syncthreads();

    for (int kt = 0; kt < nt_tiles; kt++) {
        const int buf = kt & 1;
        const bool has_next = (kt + 1) < nt_tiles;
        if (has_next) { ldgA((kt + 1) * 16); ldgB((kt + 1) * 16); }

        const float* As_ = As[buf];
        const float* Bs_ = Bs[buf];
#pragma unroll
        for (int k8 = 0; k8 < 2; k8++) {
            const int kc = k8 * 8;
            uint32_t af[4][4];
#pragma unroll
            for (int mt = 0; mt < 4; mt++) {
                const float* p = As_ + (wm + mt * 16 + g) * SROW + kc + l;
                af[mt][0] = __float_as_uint(p[0]);
                af[mt][1] = __float_as_uint(p[8 * SROW]);
                af[mt][2] = __float_as_uint(p[4]);
                af[mt][3] = __float_as_uint(p[8 * SROW + 4]);
            }
            uint32_t bfr[4][2];
#pragma unroll
            for (int ntile = 0; ntile < 4; ntile++) {
                const float* q = Bs_ + (wn + ntile * 8 + g) * SROW + kc + l;
                bfr[ntile][0] = __float_as_uint(q[0]);
                bfr[ntile][1] = __float_as_uint(q[4]);
            }
#pragma unroll
            for (int mt = 0; mt < 4; mt++)
#pragma unroll
                for (int ntile = 0; ntile < 4; ntile++)
                    mma_tf32(acc[mt][ntile], af[mt], bfr[ntile]);
        }

        if (has_next) {
            stsAB(buf ^ 1);
            __syncthreads();
        }
    }

    // ---- epilogue ----
    float* Cp = C;
    if (MODE == 4 || MODE == 5) Cp = C + (size_t)zi * M * ldc;

#pragma unroll
    for (int mt = 0; mt < 4; mt++) {
        const int r0l = wm + mt * 16 + g;
        const int r1l = r0l + 8;
        long gm0 = m0 + r0l, gm1 = m0 + r1l;
        bool ok0 = true, ok1 = true;
        float *crow0, *crow1;
        if (MODE == 3) {
            int a0 = sridx[r0l], a1 = sridx[r1l];
            ok0 = (a0 >= 0); ok1 = (a1 >= 0);
            crow0 = ok0 ? (Cp + (size_t)a0 * ldc) : nullptr;
            crow1 = ok1 ? (Cp + (size_t)a1 * ldc) : nullptr;
        } else {
            crow0 = Cp + (size_t)gm0 * ldc;
            crow1 = Cp + (size_t)gm1 * ldc;
        }
#pragma unroll
        for (int ntile = 0; ntile < 4; ntile++) {
            const int cn = wn + ntile * 8 + 2 * l;
            long gn = n0 + cn;
            if (MODE == 3 && gn >= N) continue;
            float2 v0 = make_float2(acc[mt][ntile][0], acc[mt][ntile][1]);
            float2 v1 = make_float2(acc[mt][ntile][2], acc[mt][ntile][3]);
            if (MODE == 0 || MODE == 3) {
                float bx = bias[gn], by = bias[gn + 1];
                if (MODE == 0 && bias2) { bx += bias2[gn]; by += bias2[gn + 1]; }
                v0.x += bx; v0.y += by; v1.x += bx; v1.y += by;
            }
            if (ok0) *(float2*)(crow0 + gn) = v0;
            if (ok1) *(float2*)(crow1 + gn) = v1;
        }
    }
}

// ---------------------------------------------------------------------------
// Support kernels
// ---------------------------------------------------------------------------
__global__ void compact_rows(const int* __restrict__ lengths,
                             int* __restrict__ rowidx, int* __restrict__ mact)
{
    __shared__ int off[BB + 1];
    __shared__ int cnts[BB];
    int b = threadIdx.x;
    int cnt = min(lengths[b] + 1, TT);
    cnts[b] = cnt;
    __syncthreads();
    if (b == 0) {
        int s = 0;
        for (int i = 0; i < BB; i++) { off[i] = s; s += cnts[i]; }
        off[BB] = s;
        *mact = s;
    }
    __syncthreads();
    int o = off[b];
    for (int j = 0; j < cnt; j++) rowidx[o + j] = b * TT + j;
}

__global__ void zero_masked(const int* __restrict__ lengths, float* __restrict__ out)
{
    int r = blockIdx.x;
    int b = r / TT, t = r % TT;
    if (lengths[b] >= t) return;
    float4 zz = make_float4(0.f, 0.f, 0.f, 0.f);
    float4* row = (float4*)(out + (size_t)r * VV);
    for (int i = threadIdx.x; i < VV / 4; i += blockDim.x) row[i] = zz;
}

__global__ void gather_kernel(const int* __restrict__ cap,
                              const float* __restrict__ emb,
                              float* __restrict__ xe)
{
    int r = blockIdx.x;
    int i = threadIdx.x;
    const float4* src = (const float4*)(emb + (size_t)cap[r] * EE);
    ((float4*)(xe + (size_t)r * EE))[i] = src[i];
}

// ---------------------------------------------------------------------------
// Fused attention (reads split-K a_h partials + b_h2a)
// ---------------------------------------------------------------------------
__global__ void __launch_bounds__(256)
attn_fused(const float* __restrict__ a_feat,
           const float* __restrict__ ahp,
           const float* __restrict__ b_h2a,
           const float* __restrict__ w_a,
           const float* __restrict__ b_a,
           const float* __restrict__ feature,
           float* __restrict__ z)
{
    int b = blockIdx.x;
    int tid = threadIdx.x;
    int warp = tid >> 5, lane = tid & 31;
    __shared__ __align__(16) float s_ah[DD];
    __shared__ __align__(16) float s_w[DD];
    __shared__ float s_sc[FF];
    __shared__ float red[8];
    __shared__ float bmax, bsum;

    for (int i = tid; i < DD / 4; i += 256) {
        float4 v = ((const float4*)b_h2a)[i];
#pragma unroll
        for (int zp = 0; zp < 4; zp++) {
            float4 p = ((const float4*)(ahp + ((size_t)zp * BB + b) * DD))[i];
            v.x += p.x; v.y += p.y; v.z += p.z; v.w += p.w;
        }
        ((float4*)s_ah)[i] = v;
        ((float4*)s_w)[i]  = ((const float4*)w_a)[i];
    }
    __syncthreads();

    float ba = b_a[0];
    for (int f = warp; f < FF; f += 8) {
        const float4* af = (const float4*)(a_feat + ((size_t)b * FF + f) * DD);
        float s = 0.f;
#pragma unroll 4
        for (int k = lane; k < DD / 4; k += 32) {
            float4 a = af[k];
            float4 h4 = ((const float4*)s_ah)[k];
            float4 w4 = ((const float4*)s_w)[k];
            s += fmaxf(a.x + h4.x, 0.f) * w4.x
               + fmaxf(a.y + h4.y, 0.f) * w4.y
               + fmaxf(a.z + h4.z, 0.f) * w4.z
               + fmaxf(a.w + h4.w, 0.f) * w4.w;
        }
#pragma unroll
        for (int o = 16; o; o >>= 1) s += __shfl_down_sync(0xffffffffu, s, o);
        if (lane == 0) s_sc[f] = s + ba;
    }
    __syncthreads();

    float v = (tid < FF) ? s_sc[tid] : -3.0e38f;
    float m = v;
#pragma unroll
    for (int o = 16; o; o >>= 1) m = fmaxf(m, __shfl_xor_sync(0xffffffffu, m, o));
    if (lane == 0) red[warp] = m;
    __syncthreads();
    if (tid == 0) {
        float x = red[0];
        for (int w = 1; w < 8; w++) x = fmaxf(x, red[w]);
        bmax = x;
    }
    __syncthreads();
    float e = (tid < FF) ? expf(v - bmax) : 0.f;
    float s = e;
#pragma unroll
    for (int o = 16; o; o >>= 1) s += __shfl_xor_sync(0xffffffffu, s, o);
    if (lane == 0) red[warp] = s;
    __syncthreads();
    if (tid == 0) {
        float x = 0.f;
        for (int w = 0; w < 8; w++) x += red[w];
        bsum = x;
    }
    __syncthreads();
    if (tid < FF) s_sc[tid] = e / bsum;
    __syncthreads();

    const float* fp = feature + (size_t)b * FF * DD;
    for (int d = tid; d < DD; d += 256) {
        float s0 = 0.f, s1 = 0.f, s2 = 0.f, s3 = 0.f;
        for (int f = 0; f < FF; f += 4) {
            s0 += s_sc[f + 0] * fp[(size_t)(f + 0) * DD + d];
            s1 += s_sc[f + 1] * fp[(size_t)(f + 1) * DD + d];
            s2 += s_sc[f + 2] * fp[(size_t)(f + 2) * DD + d];
            s3 += s_sc[f + 3] * fp[(size_t)(f + 3) * DD + d];
        }
        z[(size_t)b * DD + d] = (s0 + s1) + (s2 + s3);
    }
}

__global__ void zmean_kernel(const float* __restrict__ feature,
                             float* __restrict__ z)
{
    int b = blockIdx.x;
    int d = blockIdx.y * 128 + threadIdx.x;
    const float* fp = feature + (size_t)b * FF * DD + d;
    float s0 = 0.f, s1 = 0.f, s2 = 0.f, s3 = 0.f;
    for (int f = 0; f < FF; f += 4) {
        s0 += fp[(size_t)(f + 0) * DD];
        s1 += fp[(size_t)(f + 1) * DD];
        s2 += fp[(size_t)(f + 2) * DD];
        s3 += fp[(size_t)(f + 3) * DD];
    }
    z[b * DD + d] = ((s0 + s1) + (s2 + s3)) * (1.0f / FF);
}

__device__ __forceinline__ float sigmoidf_(float x) { return 1.f / (1.f + expf(-x)); }

// LSTM pointwise: sums 3 split-K gate partials + precomputed gemb slice.
__global__ void lstm_kernel(const float* __restrict__ gp,
                            const float* __restrict__ gemb,
                            const int* __restrict__ lengths, int t,
                            float* __restrict__ h, float* __restrict__ c,
                            float* __restrict__ hall)
{
    int idx = blockIdx.x * blockDim.x + threadIdx.x;
    if (idx >= BB * HH) return;
    int b = idx >> 10;
    int hh = idx & (HH - 1);
    const size_t S = (size_t)BB * 4 * HH;
    const size_t base = (size_t)b * 4 * HH;
    const float* g0 = gp + base;
    const float* g1 = gp + S + base;
    const float* g2 = gp + 2 * S + base;
    const float* ge = gemb + ((size_t)b * TT + t) * 4 * HH;

    float vi = g0[hh] + g1[hh] + g2[hh] + ge[hh];
    float vf = g0[HH + hh] + g1[HH + hh] + g2[HH + hh] + ge[HH + hh];
    float vg = g0[2 * HH + hh] + g1[2 * HH + hh] + g2[2 * HH + hh] + ge[2 * HH + hh];
    float vo = g0[3 * HH + hh] + g1[3 * HH + hh] + g2[3 * HH + hh] + ge[3 * HH + hh];

    float ii = sigmoidf_(vi);
    float ff = sigmoidf_(vf);
    float gg = tanhf(vg);
    float oo = sigmoidf_(vo);
    float cn = ff * c[idx] + ii * gg;
    float hn = oo * tanhf(cn);
    hall[((size_t)b * TT + t) * HH + hh] = hn;
    if (lengths[b] >= t) {
        h[idx] = hn;
        c[idx] = cn;
    }
}

// ---------------------------------------------------------------------------
// Host orchestration (multi-stream fork/join inside graph capture)
// ---------------------------------------------------------------------------
extern "C" void kernel_launch(void* const* d_in, const int* in_sizes, int n_in,
                              void* d_out, int out_size)
{
    const float* feature = (const float*)d_in[0];
    const int*   captions = (const int*)d_in[1];
    const int*   lengths = (const int*)d_in[2];
    const float* emb    = (const float*)d_in[3];
    const float* W_ih   = (const float*)d_in[4];
    const float* b_ih   = (const float*)d_in[5];
    const float* W_hh   = (const float*)d_in[6];
    const float* b_hh   = (const float*)d_in[7];
    const float* W_fc   = (const float*)d_in[8];
    const float* b_fc   = (const float*)d_in[9];
    const float* W_h2a  = (const float*)d_in[10];
    const float* b_h2a  = (const float*)d_in[11];
    const float* W_f2a  = (const float*)d_in[12];
    const float* b_f2a  = (const float*)d_in[13];
    const float* W_a2a  = (const float*)d_in[14];
    const float* b_a2a  = (const float*)d_in[15];
    float* out = (float*)d_out;

    float *a_feat, *x_e, *gemb, *hall, *h, *c, *z, *z0, *ahp, *gatesp;
    int *rowidx, *mact;
    cudaGetSymbolAddress((void**)&a_feat, g_a_feat);
    cudaGetSymbolAddress((void**)&x_e,    g_x_emb);
    cudaGetSymbolAddress((void**)&gemb,   g_gemb);
    cudaGetSymbolAddress((void**)&hall,   g_hall);
    cudaGetSymbolAddress((void**)&h,      g_h);
    cudaGetSymbolAddress((void**)&c,      g_c);
    cudaGetSymbolAddress((void**)&z,      g_z);
    cudaGetSymbolAddress((void**)&z0,     g_z0);
    cudaGetSymbolAddress((void**)&ahp,    g_ahp);
    cudaGetSymbolAddress((void**)&gatesp, g_gatesp);
    cudaGetSymbolAddress((void**)&rowidx, g_rowidx);
    cudaGetSymbolAddress((void**)&mact,   g_mact);

    // One-time side stream + events (handles reused; identical work every call)
    static cudaStream_t s1 = nullptr;
    static cudaEvent_t evFork = nullptr, evA = nullptr, evH = nullptr, evG = nullptr;
    if (s1 == nullptr) {
        cudaStreamCreateWithFlags(&s1, cudaStreamNonBlocking);
        cudaEventCreateWithFlags(&evFork, cudaEventDisableTiming);
        cudaEventCreateWithFlags(&evA,    cudaEventDisableTiming);
        cudaEventCreateWithFlags(&evH,    cudaEventDisableTiming);
        cudaEventCreateWithFlags(&evG,    cudaEventDisableTiming);
    }

    cudaMemsetAsync(h, 0, (size_t)BB * HH * sizeof(float));
    cudaMemsetAsync(c, 0, (size_t)BB * HH * sizeof(float));
    gather_kernel<<<BB * TT, 128>>>(captions, emb, x_e);
    compact_rows<<<1, BB>>>(lengths, rowidx, mact);

    // Fork: a_feat GEMM + zero_masked run on side stream (joined before t=1 attn)
    cudaEventRecord(evFork, 0);
    cudaStreamWaitEvent(s1, evFork, 0);
    mma_gemm<0><<<dim3(196, 4), 256, 0, s1>>>(
        feature, DD, nullptr, W_f2a, DD, nullptr,
        b_f2a, nullptr,
        a_feat, DD, BB * FF, DD, DD, 0, nullptr, nullptr);
    zero_masked<<<BB * TT, 256, 0, s1>>>(lengths, out);
    cudaEventRecord(evA, s1);

    // g_emb = x_emb @ W_ih[:, D:]^T + b_ih + b_hh   [2560, 512] x [4096, 512]
    mma_gemm<0><<<dim3(20, 32), 256>>>(
        x_e, EE, nullptr, W_ih + DD, DD + EE, nullptr,
        b_ih, b_hh,
        gemb, 4 * HH, BB * TT, 4 * HH, EE, 0, nullptr, nullptr);

    zmean_kernel<<<dim3(BB, DD / 128), 128>>>(feature, z0);

    for (int t = 0; t < TT; t++) {
        if (t == 0) {
            // h = 0: run all 3 gate partials serially (cheap, no attention)
            mma_gemm<4><<<dim3(1, 32, 3), 256>>>(
                z0, 0, h, W_ih, 0, W_hh,
                nullptr, nullptr,
                gatesp, 4 * HH, BB, 4 * HH, 512, 0, nullptr, nullptr);
            lstm_kernel<<<(BB * HH + 255) / 256, 256>>>(gatesp, gemb, lengths, t,
                                                        h, c, hall);
            continue;
        }

        // Fork: gates h-part (zi=1,2) depends only on h -> side stream,
        // concurrent with a_h -> attn -> gates_z on the main stream.
        cudaEventRecord(evH, 0);
        cudaStreamWaitEvent(s1, evH, 0);
        mma_gemm<4><<<dim3(1, 32, 2), 256, 0, s1>>>(
            nullptr, 0, h, W_ih, 0, W_hh,
            nullptr, nullptr,
            gatesp, 4 * HH, BB, 4 * HH, 512, 1, nullptr, nullptr);
        cudaEventRecord(evG, s1);

        // a_h partials: h @ W_h2a^T, split-K=4 (chunks of 256)
        mma_gemm<5><<<dim3(1, 4, 4), 256>>>(
            h, HH, nullptr, W_h2a, HH, nullptr,
            nullptr, nullptr,
            ahp, DD, BB, DD, 256, 0, nullptr, nullptr);

        if (t == 1) cudaStreamWaitEvent(0, evA, 0);  // a_feat ready
        attn_fused<<<BB, 256>>>(a_feat, ahp, b_h2a, W_a2a, b_a2a, feature, z);

        // gates z-part (zi=0)
        mma_gemm<4><<<dim3(1, 32, 1), 256>>>(
            z, 0, h, W_ih, 0, W_hh,
            nullptr, nullptr,
            gatesp, 4 * HH, BB, 4 * HH, 512, 0, nullptr, nullptr);

        cudaStreamWaitEvent(0, evG, 0);  // join gates h-part
        lstm_kernel<<<(BB * HH + 255) / 256, 256>>>(gatesp, gemb, lengths, t,
                                                    h, c, hall);
    }

    // preds[active rows] = h_all @ W_fc^T + b_fc    [Mact, 1024] x [10000, 1024]
    mma_gemm<3><<<dim3(20, 79), 256>>>(
        hall, HH, nullptr, W_fc, HH, nullptr,
        b_fc, nullptr,
        out, VV, BB * TT, VV, HH, 0, rowidx, mact);
}

// round 9
// speedup vs baseline: 2.7300x; 1.2116x over previous
#include <cuda_runtime.h>
#include <cstdint>
#include <cstddef>

// Problem constants
#define BB 128
#define TT 20
#define VV 10000
#define EE 512
#define HH 1024
#define FF 196
#define DD 512

// ---------------------------------------------------------------------------
// Device scratch
// ---------------------------------------------------------------------------
__device__ float g_a_feat[(size_t)BB * FF * DD];
__device__ float g_x_emb[(size_t)BB * TT * EE];
__device__ float g_gemb[(size_t)BB * TT * 4 * HH];
__device__ float g_hall[(size_t)BB * TT * HH];
__device__ float g_h[BB * HH];
__device__ float g_c[BB * HH];
__device__ float g_z[BB * DD];
__device__ float g_z0[BB * DD];
__device__ float g_hg[2 * BB * 4608];         // split-K=2 partials: [W_hh|W_h2a]
__device__ float g_zg[BB * 4 * HH];           // z-gates raw
__device__ int   g_rowidx[BB * TT];
__device__ int   g_mact[1];

__device__ __forceinline__ uint32_t f2tf32(float x) {
    uint32_t r;
    asm("cvt.rna.tf32.f32 %0, %1;" : "=r"(r) : "f"(x));
    return r;
}

__device__ __forceinline__ void mma_tf32(float c[4], const uint32_t a[4],
                                         const uint32_t b[2]) {
    asm volatile(
        "mma.sync.aligned.m16n8k8.row.col.f32.tf32.tf32.f32 "
        "{%0,%1,%2,%3}, {%4,%5,%6,%7}, {%8,%9}, {%0,%1,%2,%3};"
        : "+f"(c[0]), "+f"(c[1]), "+f"(c[2]), "+f"(c[3])
        : "r"(a[0]), "r"(a[1]), "r"(a[2]), "r"(a[3]), "r"(b[0]), "r"(b[1]));
}

// ---------------------------------------------------------------------------
// Tensor-core (mma.sync tf32) GEMM: C[M,N] = A[M,K] * B[N,K]^T
// CTA tile 128x128, BK=16, double-buffered smem, 8 warps of 64x32.
//   MODE 0: C = acc + bias[n] (+ bias2[n]).  M%128==0, N%128==0.
//   MODE 3: fc over compacted rows: A row = rowidx[m], m < *mact; N-bounds.
//   MODE 5: split-K partial: kofs = zi*K; raw partial -> C + zi*M*ldc.
//   MODE 7: h-GEMM: A = h (ld 1024); B row gn<4096 ? W_hh[gn] : W_h2a[gn-4096]
//           (both ld 1024); split-K kofs = zi*K; raw -> C + zi*M*ldc.
// ---------------------------------------------------------------------------
#define SROW 20

template<int MODE>
__global__ void __launch_bounds__(256, 2)
mma_gemm(const float* __restrict__ A, int lda,
         const float* __restrict__ Bm, int ldb,
         const float* __restrict__ B2,
         const float* __restrict__ bias, const float* __restrict__ bias2,
         float* __restrict__ C, int ldc,
         int M, int N, int K,
         const int* __restrict__ rowidx, const int* __restrict__ mact)
{
    __shared__ __align__(16) float As[2][128 * SROW];
    __shared__ __align__(16) float Bs[2][128 * SROW];
    __shared__ int sridx[128];

    const int tid = threadIdx.x;
    const int wid = tid >> 5;
    const int lane = tid & 31;
    const int g = lane >> 2;
    const int l = lane & 3;
    const int wm = (wid >> 2) * 64;
    const int wn = (wid & 3) * 32;
    const long m0 = (long)blockIdx.x * 128;
    const long n0 = (long)blockIdx.y * 128;
    const int zi = blockIdx.z;
    const int kofs = (MODE == 5 || MODE == 7) ? zi * K : 0;

    int Mact = M;
    if (MODE == 3) {
        Mact = *mact;
        if (m0 >= Mact) return;
        if (tid < 128) {
            long gm = m0 + tid;
            sridx[tid] = (gm < Mact) ? rowidx[gm] : -1;
        }
        __syncthreads();
    }

    float acc[4][4][4];
#pragma unroll
    for (int i = 0; i < 4; i++)
#pragma unroll
        for (int j = 0; j < 4; j++)
#pragma unroll
            for (int k = 0; k < 4; k++) acc[i][j][k] = 0.f;

    float4 va[2], vb[2];
    auto ldgA = [&](int k0) {
#pragma unroll
        for (int i = 0; i < 2; i++) {
            int lin = tid + i * 256;
            int r = lin >> 2, kq = lin & 3;
            int gk = k0 + kq * 4 + kofs;
            if (MODE == 3) {
                int ar = sridx[r];
                va[i] = (ar >= 0) ? *(const float4*)(A + (size_t)ar * lda + gk)
                                  : make_float4(0.f, 0.f, 0.f, 0.f);
            } else {
                va[i] = *(const float4*)(A + (size_t)(m0 + r) * lda + gk);
            }
        }
    };
    auto ldgB = [&](int k0) {
#pragma unroll
        for (int i = 0; i < 2; i++) {
            int lin = tid + i * 256;
            int r = lin >> 2, kq = lin & 3;
            long gn = n0 + r;
            int gk = k0 + kq * 4 + kofs;
            if (MODE == 7) {
                const float* p = (gn < 4096)
                    ? (Bm + (size_t)gn * 1024 + gk)
                    : (B2 + (size_t)(gn - 4096) * 1024 + gk);
                vb[i] = *(const float4*)p;
            } else if (MODE == 3) {
                vb[i] = (gn < N) ? *(const float4*)(Bm + (size_t)gn * ldb + gk)
                                 : make_float4(0.f, 0.f, 0.f, 0.f);
            } else {
                vb[i] = *(const float4*)(Bm + (size_t)gn * ldb + gk);
            }
        }
    };
    auto stsAB = [&](int buf) {
#pragma unroll
        for (int i = 0; i < 2; i++) {
            int lin = tid + i * 256;
            int r = lin >> 2, kq = lin & 3;
            float4 ta, tb;
            ta.x = __uint_as_float(f2tf32(va[i].x));
            ta.y = __uint_as_float(f2tf32(va[i].y));
            ta.z = __uint_as_float(f2tf32(va[i].z));
            ta.w = __uint_as_float(f2tf32(va[i].w));
            tb.x = __uint_as_float(f2tf32(vb[i].x));
            tb.y = __uint_as_float(f2tf32(vb[i].y));
            tb.z = __uint_as_float(f2tf32(vb[i].z));
            tb.w = __uint_as_float(f2tf32(vb[i].w));
            *(float4*)&As[buf][r * SROW + kq * 4] = ta;
            *(float4*)&Bs[buf][r * SROW + kq * 4] = tb;
        }
    };

    const int nt_tiles = K >> 4;

    ldgA(0); ldgB(0);
    stsAB(0);
    __syncthreads();

    for (int kt = 0; kt < nt_tiles; kt++) {
        const int buf = kt & 1;
        const bool has_next = (kt + 1) < nt_tiles;
        if (has_next) { ldgA((kt + 1) * 16); ldgB((kt + 1) * 16); }

        const float* As_ = As[buf];
        const float* Bs_ = Bs[buf];
#pragma unroll
        for (int k8 = 0; k8 < 2; k8++) {
            const int kc = k8 * 8;
            uint32_t af[4][4];
#pragma unroll
            for (int mt = 0; mt < 4; mt++) {
                const float* p = As_ + (wm + mt * 16 + g) * SROW + kc + l;
                af[mt][0] = __float_as_uint(p[0]);
                af[mt][1] = __float_as_uint(p[8 * SROW]);
                af[mt][2] = __float_as_uint(p[4]);
                af[mt][3] = __float_as_uint(p[8 * SROW + 4]);
            }
            uint32_t bfr[4][2];
#pragma unroll
            for (int ntile = 0; ntile < 4; ntile++) {
                const float* q = Bs_ + (wn + ntile * 8 + g) * SROW + kc + l;
                bfr[ntile][0] = __float_as_uint(q[0]);
                bfr[ntile][1] = __float_as_uint(q[4]);
            }
#pragma unroll
            for (int mt = 0; mt < 4; mt++)
#pragma unroll
                for (int ntile = 0; ntile < 4; ntile++)
                    mma_tf32(acc[mt][ntile], af[mt], bfr[ntile]);
        }

        if (has_next) {
            stsAB(buf ^ 1);
            __syncthreads();
        }
    }

    // ---- epilogue ----
    float* Cp = C;
    if (MODE == 5 || MODE == 7) Cp = C + (size_t)zi * M * ldc;

#pragma unroll
    for (int mt = 0; mt < 4; mt++) {
        const int r0l = wm + mt * 16 + g;
        const int r1l = r0l + 8;
        long gm0 = m0 + r0l, gm1 = m0 + r1l;
        bool ok0 = true, ok1 = true;
        float *crow0, *crow1;
        if (MODE == 3) {
            int a0 = sridx[r0l], a1 = sridx[r1l];
            ok0 = (a0 >= 0); ok1 = (a1 >= 0);
            crow0 = ok0 ? (Cp + (size_t)a0 * ldc) : nullptr;
            crow1 = ok1 ? (Cp + (size_t)a1 * ldc) : nullptr;
        } else {
            crow0 = Cp + (size_t)gm0 * ldc;
            crow1 = Cp + (size_t)gm1 * ldc;
        }
#pragma unroll
        for (int ntile = 0; ntile < 4; ntile++) {
            const int cn = wn + ntile * 8 + 2 * l;
            long gn = n0 + cn;
            if (MODE == 3 && gn >= N) continue;
            float2 v0 = make_float2(acc[mt][ntile][0], acc[mt][ntile][1]);
            float2 v1 = make_float2(acc[mt][ntile][2], acc[mt][ntile][3]);
            if (MODE == 0 || MODE == 3) {
                float bx = bias[gn], by = bias[gn + 1];
                if (MODE == 0 && bias2) { bx += bias2[gn]; by += bias2[gn + 1]; }
                v0.x += bx; v0.y += by; v1.x += bx; v1.y += by;
            }
            if (ok0) *(float2*)(crow0 + gn) = v0;
            if (ok1) *(float2*)(crow1 + gn) = v1;
        }
    }
}

// ---------------------------------------------------------------------------
// Support kernels
// ---------------------------------------------------------------------------
__global__ void compact_rows(const int* __restrict__ lengths,
                             int* __restrict__ rowidx, int* __restrict__ mact)
{
    __shared__ int off[BB + 1];
    __shared__ int cnts[BB];
    int b = threadIdx.x;
    int cnt = min(lengths[b] + 1, TT);
    cnts[b] = cnt;
    __syncthreads();
    if (b == 0) {
        int s = 0;
        for (int i = 0; i < BB; i++) { off[i] = s; s += cnts[i]; }
        off[BB] = s;
        *mact = s;
    }
    __syncthreads();
    int o = off[b];
    for (int j = 0; j < cnt; j++) rowidx[o + j] = b * TT + j;
}

__global__ void zero_masked(const int* __restrict__ lengths, float* __restrict__ out)
{
    int r = blockIdx.x;
    int b = r / TT, t = r % TT;
    if (lengths[b] >= t) return;
    float4 zz = make_float4(0.f, 0.f, 0.f, 0.f);
    float4* row = (float4*)(out + (size_t)r * VV);
    for (int i = threadIdx.x; i < VV / 4; i += blockDim.x) row[i] = zz;
}

__global__ void gather_kernel(const int* __restrict__ cap,
                              const float* __restrict__ emb,
                              float* __restrict__ xe)
{
    int r = blockIdx.x;
    int i = threadIdx.x;
    const float4* src = (const float4*)(emb + (size_t)cap[r] * EE);
    ((float4*)(xe + (size_t)r * EE))[i] = src[i];
}

// ---------------------------------------------------------------------------
// Fused attention (fp32; a_h from hg partial cols 4096+ of both splits)
// ---------------------------------------------------------------------------
__global__ void __launch_bounds__(256)
attn_fused(const float* __restrict__ a_feat,
           const float* __restrict__ hg,
           const float* __restrict__ b_h2a,
           const float* __restrict__ w_a,
           const float* __restrict__ b_a,
           const float* __restrict__ feature,
           float* __restrict__ z)
{
    int b = blockIdx.x;
    int tid = threadIdx.x;
    int warp = tid >> 5, lane = tid & 31;
    __shared__ __align__(16) float s_ah[DD];
    __shared__ __align__(16) float s_w[DD];
    __shared__ float s_sc[FF];
    __shared__ __align__(16) float s_zp[2][DD];
    __shared__ float red[8];
    __shared__ float bmax, bsum;

    const size_t HGS = (size_t)BB * 4608;
    for (int i = tid; i < DD / 4; i += 256) {
        float4 v = ((const float4*)b_h2a)[i];
        float4 p0 = *(const float4*)(hg + (size_t)b * 4608 + 4096 + i * 4);
        float4 p1 = *(const float4*)(hg + HGS + (size_t)b * 4608 + 4096 + i * 4);
        v.x += p0.x + p1.x; v.y += p0.y + p1.y;
        v.z += p0.z + p1.z; v.w += p0.w + p1.w;
        ((float4*)s_ah)[i] = v;
        ((float4*)s_w)[i]  = ((const float4*)w_a)[i];
    }
    __syncthreads();

    float ba = b_a[0];
    for (int f = warp; f < FF; f += 8) {
        const float4* af = (const float4*)(a_feat + ((size_t)b * FF + f) * DD);
        float s = 0.f;
#pragma unroll 4
        for (int k = lane; k < DD / 4; k += 32) {
            float4 a = af[k];
            float4 h4 = ((const float4*)s_ah)[k];
            float4 w4 = ((const float4*)s_w)[k];
            s += fmaxf(a.x + h4.x, 0.f) * w4.x
               + fmaxf(a.y + h4.y, 0.f) * w4.y
               + fmaxf(a.z + h4.z, 0.f) * w4.z
               + fmaxf(a.w + h4.w, 0.f) * w4.w;
        }
#pragma unroll
        for (int o = 16; o; o >>= 1) s += __shfl_down_sync(0xffffffffu, s, o);
        if (lane == 0) s_sc[f] = s + ba;
    }
    __syncthreads();

    // softmax over FF = 196
    float v = (tid < FF) ? s_sc[tid] : -3.0e38f;
    float m = v;
#pragma unroll
    for (int o = 16; o; o >>= 1) m = fmaxf(m, __shfl_xor_sync(0xffffffffu, m, o));
    if (lane == 0) red[warp] = m;
    __syncthreads();
    if (tid == 0) {
        float x = red[0];
        for (int w = 1; w < 8; w++) x = fmaxf(x, red[w]);
        bmax = x;
    }
    __syncthreads();
    float e = (tid < FF) ? expf(v - bmax) : 0.f;
    float s = e;
#pragma unroll
    for (int o = 16; o; o >>= 1) s += __shfl_xor_sync(0xffffffffu, s, o);
    if (lane == 0) red[warp] = s;
    __syncthreads();
    if (tid == 0) {
        float x = 0.f;
        for (int w = 0; w < 8; w++) x += red[w];
        bsum = x;
    }
    __syncthreads();
    if (tid < FF) s_sc[tid] = e / bsum;
    __syncthreads();

    // z phase: half 0 sums f in [0,98), half 1 sums f in [98,196)
    {
        int half = tid >> 7;
        int dt = (tid & 127) * 4;
        int f0 = half ? 98 : 0;
        int f1 = half ? FF : 98;
        const float4* fp = (const float4*)(feature + (size_t)b * FF * DD) + (dt >> 2);
        float a0 = 0.f, a1 = 0.f, a2 = 0.f, a3 = 0.f;
        for (int f = f0; f < f1; f++) {
            float4 q = fp[(size_t)f * (DD / 4)];
            float al = s_sc[f];
            a0 += al * q.x; a1 += al * q.y;
            a2 += al * q.z; a3 += al * q.w;
        }
        *(float4*)&s_zp[half][dt] = make_float4(a0, a1, a2, a3);
    }
    __syncthreads();
    if (tid < 128) {
        int dt = tid * 4;
        float4 u = *(const float4*)&s_zp[0][dt];
        float4 w = *(const float4*)&s_zp[1][dt];
        u.x += w.x; u.y += w.y; u.z += w.z; u.w += w.w;
        *(float4*)(z + (size_t)b * DD + dt) = u;
    }
}

__global__ void zmean_kernel(const float* __restrict__ feature,
                             float* __restrict__ z)
{
    int b = blockIdx.x;
    int d = blockIdx.y * 128 + threadIdx.x;
    const float* fp = feature + (size_t)b * FF * DD + d;
    float s0 = 0.f, s1 = 0.f, s2 = 0.f, s3 = 0.f;
    for (int f = 0; f < FF; f += 4) {
        s0 += fp[(size_t)(f + 0) * DD];
        s1 += fp[(size_t)(f + 1) * DD];
        s2 += fp[(size_t)(f + 2) * DD];
        s3 += fp[(size_t)(f + 3) * DD];
    }
    z[b * DD + d] = ((s0 + s1) + (s2 + s3)) * (1.0f / FF);
}

__device__ __forceinline__ float sigmoidf_(float x) { return 1.f / (1.f + expf(-x)); }

// LSTM pointwise: gates = zg + hg[0][:, :4096] + hg[1][:, :4096] + gemb.
__global__ void lstm_kernel(const float* __restrict__ zg,
                            const float* __restrict__ hg,
                            const float* __restrict__ gemb,
                            const int* __restrict__ lengths, int t,
                            float* __restrict__ h, float* __restrict__ c,
                            float* __restrict__ hall)
{
    int idx = blockIdx.x * blockDim.x + threadIdx.x;
    if (idx >= BB * HH) return;
    int b = idx >> 10;
    int hh = idx & (HH - 1);
    const size_t HGS = (size_t)BB * 4608;
    const float* zgb = zg + (size_t)b * 4096;
    const float* h0b = hg + (size_t)b * 4608;
    const float* h1b = hg + HGS + (size_t)b * 4608;
    const float* ge  = gemb + ((size_t)b * TT + t) * 4 * HH;

    float vi = zgb[hh]          + h0b[hh]          + h1b[hh]          + ge[hh];
    float vf = zgb[HH + hh]     + h0b[HH + hh]     + h1b[HH + hh]     + ge[HH + hh];
    float vg = zgb[2 * HH + hh] + h0b[2 * HH + hh] + h1b[2 * HH + hh] + ge[2 * HH + hh];
    float vo = zgb[3 * HH + hh] + h0b[3 * HH + hh] + h1b[3 * HH + hh] + ge[3 * HH + hh];

    float ii = sigmoidf_(vi);
    float ff = sigmoidf_(vf);
    float gg = tanhf(vg);
    float oo = sigmoidf_(vo);
    float cn = ff * c[idx] + ii * gg;
    float hn = oo * tanhf(cn);
    hall[((size_t)b * TT + t) * HH + hh] = hn;
    if (lengths[b] >= t) {
        h[idx] = hn;
        c[idx] = cn;
    }
}

// ---------------------------------------------------------------------------
// Host orchestration
// ---------------------------------------------------------------------------
extern "C" void kernel_launch(void* const* d_in, const int* in_sizes, int n_in,
                              void* d_out, int out_size)
{
    const float* feature = (const float*)d_in[0];
    const int*   captions = (const int*)d_in[1];
    const int*   lengths = (const int*)d_in[2];
    const float* emb    = (const float*)d_in[3];
    const float* W_ih   = (const float*)d_in[4];
    const float* b_ih   = (const float*)d_in[5];
    const float* W_hh   = (const float*)d_in[6];
    const float* b_hh   = (const float*)d_in[7];
    const float* W_fc   = (const float*)d_in[8];
    const float* b_fc   = (const float*)d_in[9];
    const float* W_h2a  = (const float*)d_in[10];
    const float* b_h2a  = (const float*)d_in[11];
    const float* W_f2a  = (const float*)d_in[12];
    const float* b_f2a  = (const float*)d_in[13];
    const float* W_a2a  = (const float*)d_in[14];
    const float* b_a2a  = (const float*)d_in[15];
    float* out = (float*)d_out;

    float *a_feat, *x_e, *gemb, *hall, *h, *c, *z, *z0, *hg, *zg;
    int *rowidx, *mact;
    cudaGetSymbolAddress((void**)&a_feat, g_a_feat);
    cudaGetSymbolAddress((void**)&x_e,    g_x_emb);
    cudaGetSymbolAddress((void**)&gemb,   g_gemb);
    cudaGetSymbolAddress((void**)&hall,   g_hall);
    cudaGetSymbolAddress((void**)&h,      g_h);
    cudaGetSymbolAddress((void**)&c,      g_c);
    cudaGetSymbolAddress((void**)&z,      g_z);
    cudaGetSymbolAddress((void**)&z0,     g_z0);
    cudaGetSymbolAddress((void**)&hg,     g_hg);
    cudaGetSymbolAddress((void**)&zg,     g_zg);
    cudaGetSymbolAddress((void**)&rowidx, g_rowidx);
    cudaGetSymbolAddress((void**)&mact,   g_mact);

    static cudaStream_t s1 = nullptr;
    static cudaEvent_t evFork = nullptr, evA = nullptr;
    if (s1 == nullptr) {
        cudaStreamCreateWithFlags(&s1, cudaStreamNonBlocking);
        cudaEventCreateWithFlags(&evFork, cudaEventDisableTiming);
        cudaEventCreateWithFlags(&evA,    cudaEventDisableTiming);
    }

    cudaMemsetAsync(h,  0, (size_t)BB * HH * sizeof(float));
    cudaMemsetAsync(c,  0, (size_t)BB * HH * sizeof(float));
    cudaMemsetAsync(hg, 0, (size_t)2 * BB * 4608 * sizeof(float));
    gather_kernel<<<BB * TT, 128>>>(captions, emb, x_e);
    compact_rows<<<1, BB>>>(lengths, rowidx, mact);

    // Side stream: a_feat GEMM + zero_masked
    cudaEventRecord(evFork, 0);
    cudaStreamWaitEvent(s1, evFork, 0);
    mma_gemm<0><<<dim3(196, 4), 256, 0, s1>>>(
        feature, DD, W_f2a, DD, nullptr,
        b_f2a, nullptr,
        a_feat, DD, BB * FF, DD, DD, nullptr, nullptr);
    zero_masked<<<BB * TT, 256, 0, s1>>>(lengths, out);
    cudaEventRecord(evA, s1);

    // g_emb = x_emb @ W_ih[:, D:]^T + b_ih + b_hh   [2560, 512] x [4096, 512]
    mma_gemm<0><<<dim3(20, 32), 256>>>(
        x_e, EE, W_ih + DD, DD + EE, nullptr,
        b_ih, b_hh,
        gemb, 4 * HH, BB * TT, 4 * HH, EE, nullptr, nullptr);

    zmean_kernel<<<dim3(BB, DD / 128), 128>>>(feature, z0);

    for (int t = 0; t < TT; t++) {
        if (t > 0) {
            // hg = h @ [W_hh | W_h2a]^T, split-K=2 partials [2][128][4608]
            mma_gemm<7><<<dim3(1, 36, 2), 256>>>(
                h, HH, W_hh, HH, W_h2a,
                nullptr, nullptr,
                hg, 4608, BB, 4608, 512, nullptr, nullptr);

            if (t == 1) cudaStreamWaitEvent(0, evA, 0);  // a_feat ready
            attn_fused<<<BB, 256>>>(a_feat, hg, b_h2a, W_a2a, b_a2a, feature, z);
        }

        // zg = z @ W_ih[:, :512]^T (raw)   [128, 4096]
        mma_gemm<5><<<dim3(1, 32, 1), 256>>>(
            (t == 0) ? z0 : z, DD, W_ih, DD + EE, nullptr,
            nullptr, nullptr,
            zg, 4 * HH, BB, 4 * HH, DD, nullptr, nullptr);

        lstm_kernel<<<(BB * HH + 255) / 256, 256>>>(zg, hg, gemb, lengths, t,
                                                    h, c, hall);
    }

    // preds[active rows] = h_all @ W_fc^T + b_fc    [Mact, 1024] x [10000, 1024]
    mma_gemm<3><<<dim3(20, 79), 256>>>(
        hall, HH, W_fc, HH, nullptr,
        b_fc, nullptr,
        out, VV, BB * TT, VV, HH, rowidx, mact);
}

// round 10
// speedup vs baseline: 3.2008x; 1.1725x over previous
#include <cuda_runtime.h>
#include <cstdint>
#include <cstddef>

// Problem constants
#define BB 128
#define TT 20
#define VV 10000
#define EE 512
#define HH 1024
#define FF 196
#define DD 512

// ---------------------------------------------------------------------------
// Device scratch
// ---------------------------------------------------------------------------
__device__ float g_a_feat[(size_t)BB * FF * DD];
__device__ float g_x_emb[(size_t)BB * TT * EE];
__device__ float g_gemb[(size_t)BB * TT * 4 * HH];
__device__ float g_hall[(size_t)BB * TT * HH];
__device__ float g_h[BB * HH];
__device__ float g_c[BB * HH];
__device__ float g_z[BB * DD];
__device__ float g_z0[BB * DD];
__device__ float g_hg[4 * BB * 4608];         // split-K=4 partials: [W_hh|W_h2a]
__device__ float g_zg[2 * BB * 4 * HH];       // split-K=2 z-gates partials
__device__ int   g_rowidx[BB * TT];
__device__ int   g_mact[1];

__device__ __forceinline__ uint32_t f2tf32(float x) {
    uint32_t r;
    asm("cvt.rna.tf32.f32 %0, %1;" : "=r"(r) : "f"(x));
    return r;
}

__device__ __forceinline__ void mma_tf32(float c[4], const uint32_t a[4],
                                         const uint32_t b[2]) {
    asm volatile(
        "mma.sync.aligned.m16n8k8.row.col.f32.tf32.tf32.f32 "
        "{%0,%1,%2,%3}, {%4,%5,%6,%7}, {%8,%9}, {%0,%1,%2,%3};"
        : "+f"(c[0]), "+f"(c[1]), "+f"(c[2]), "+f"(c[3])
        : "r"(a[0]), "r"(a[1]), "r"(a[2]), "r"(a[3]), "r"(b[0]), "r"(b[1]));
}

// ---------------------------------------------------------------------------
// Tensor-core (mma.sync tf32) GEMM: C[M,N] = A[M,K] * B[N,K]^T
// CTA tile 128x128, BK=16, double-buffered smem, 8 warps of 64x32.
//   MODE 0: C = acc + bias[n] (+ bias2[n]).  M%128==0, N%128==0.
//   MODE 3: fc over compacted rows: A row = rowidx[m], m < *mact; N-bounds.
//   MODE 5: split-K partial: kofs = zi*K; raw partial -> C + zi*M*ldc.
//   MODE 7: h-GEMM: A = h (ld 1024); B row gn<4096 ? W_hh[gn] : W_h2a[gn-4096]
//           (both ld 1024); split-K kofs = zi*K; raw -> C + zi*M*ldc.
// ---------------------------------------------------------------------------
#define SROW 20

template<int MODE>
__global__ void __launch_bounds__(256, 2)
mma_gemm(const float* __restrict__ A, int lda,
         const float* __restrict__ Bm, int ldb,
         const float* __restrict__ B2,
         const float* __restrict__ bias, const float* __restrict__ bias2,
         float* __restrict__ C, int ldc,
         int M, int N, int K,
         const int* __restrict__ rowidx, const int* __restrict__ mact)
{
    __shared__ __align__(16) float As[2][128 * SROW];
    __shared__ __align__(16) float Bs[2][128 * SROW];
    __shared__ int sridx[128];

    const int tid = threadIdx.x;
    const int wid = tid >> 5;
    const int lane = tid & 31;
    const int g = lane >> 2;
    const int l = lane & 3;
    const int wm = (wid >> 2) * 64;
    const int wn = (wid & 3) * 32;
    const long m0 = (long)blockIdx.x * 128;
    const long n0 = (long)blockIdx.y * 128;
    const int zi = blockIdx.z;
    const int kofs = (MODE == 5 || MODE == 7) ? zi * K : 0;

    int Mact = M;
    if (MODE == 3) {
        Mact = *mact;
        if (m0 >= Mact) return;
        if (tid < 128) {
            long gm = m0 + tid;
            sridx[tid] = (gm < Mact) ? rowidx[gm] : -1;
        }
        __syncthreads();
    }

    float acc[4][4][4];
#pragma unroll
    for (int i = 0; i < 4; i++)
#pragma unroll
        for (int j = 0; j < 4; j++)
#pragma unroll
            for (int k = 0; k < 4; k++) acc[i][j][k] = 0.f;

    float4 va[2], vb[2];
    auto ldgA = [&](int k0) {
#pragma unroll
        for (int i = 0; i < 2; i++) {
            int lin = tid + i * 256;
            int r = lin >> 2, kq = lin & 3;
            int gk = k0 + kq * 4 + kofs;
            if (MODE == 3) {
                int ar = sridx[r];
                va[i] = (ar >= 0) ? *(const float4*)(A + (size_t)ar * lda + gk)
                                  : make_float4(0.f, 0.f, 0.f, 0.f);
            } else {
                va[i] = *(const float4*)(A + (size_t)(m0 + r) * lda + gk);
            }
        }
    };
    auto ldgB = [&](int k0) {
#pragma unroll
        for (int i = 0; i < 2; i++) {
            int lin = tid + i * 256;
            int r = lin >> 2, kq = lin & 3;
            long gn = n0 + r;
            int gk = k0 + kq * 4 + kofs;
            if (MODE == 7) {
                const float* p = (gn < 4096)
                    ? (Bm + (size_t)gn * 1024 + gk)
                    : (B2 + (size_t)(gn - 4096) * 1024 + gk);
                vb[i] = *(const float4*)p;
            } else if (MODE == 3) {
                vb[i] = (gn < N) ? *(const float4*)(Bm + (size_t)gn * ldb + gk)
                                 : make_float4(0.f, 0.f, 0.f, 0.f);
            } else {
                vb[i] = *(const float4*)(Bm + (size_t)gn * ldb + gk);
            }
        }
    };
    auto stsAB = [&](int buf) {
#pragma unroll
        for (int i = 0; i < 2; i++) {
            int lin = tid + i * 256;
            int r = lin >> 2, kq = lin & 3;
            float4 ta, tb;
            ta.x = __uint_as_float(f2tf32(va[i].x));
            ta.y = __uint_as_float(f2tf32(va[i].y));
            ta.z = __uint_as_float(f2tf32(va[i].z));
            ta.w = __uint_as_float(f2tf32(va[i].w));
            tb.x = __uint_as_float(f2tf32(vb[i].x));
            tb.y = __uint_as_float(f2tf32(vb[i].y));
            tb.z = __uint_as_float(f2tf32(vb[i].z));
            tb.w = __uint_as_float(f2tf32(vb[i].w));
            *(float4*)&As[buf][r * SROW + kq * 4] = ta;
            *(float4*)&Bs[buf][r * SROW + kq * 4] = tb;
        }
    };

    const int nt_tiles = K >> 4;

    ldgA(0); ldgB(0);
    stsAB(0);
    __syncthreads();

    for (int kt = 0; kt < nt_tiles; kt++) {
        const int buf = kt & 1;
        const bool has_next = (kt + 1) < nt_tiles;
        if (has_next) { ldgA((kt + 1) * 16); ldgB((kt + 1) * 16); }

        const float* As_ = As[buf];
        const float* Bs_ = Bs[buf];
#pragma unroll
        for (int k8 = 0; k8 < 2; k8++) {
            const int kc = k8 * 8;
            uint32_t af[4][4];
#pragma unroll
            for (int mt = 0; mt < 4; mt++) {
                const float* p = As_ + (wm + mt * 16 + g) * SROW + kc + l;
                af[mt][0] = __float_as_uint(p[0]);
                af[mt][1] = __float_as_uint(p[8 * SROW]);
                af[mt][2] = __float_as_uint(p[4]);
                af[mt][3] = __float_as_uint(p[8 * SROW + 4]);
            }
            uint32_t bfr[4][2];
#pragma unroll
            for (int ntile = 0; ntile < 4; ntile++) {
                const float* q = Bs_ + (wn + ntile * 8 + g) * SROW + kc + l;
                bfr[ntile][0] = __float_as_uint(q[0]);
                bfr[ntile][1] = __float_as_uint(q[4]);
            }
#pragma unroll
            for (int mt = 0; mt < 4; mt++)
#pragma unroll
                for (int ntile = 0; ntile < 4; ntile++)
                    mma_tf32(acc[mt][ntile], af[mt], bfr[ntile]);
        }

        if (has_next) {
            stsAB(buf ^ 1);
            __syncthreads();
        }
    }

    // ---- epilogue ----
    float* Cp = C;
    if (MODE == 5 || MODE == 7) Cp = C + (size_t)zi * M * ldc;

#pragma unroll
    for (int mt = 0; mt < 4; mt++) {
        const int r0l = wm + mt * 16 + g;
        const int r1l = r0l + 8;
        long gm0 = m0 + r0l, gm1 = m0 + r1l;
        bool ok0 = true, ok1 = true;
        float *crow0, *crow1;
        if (MODE == 3) {
            int a0 = sridx[r0l], a1 = sridx[r1l];
            ok0 = (a0 >= 0); ok1 = (a1 >= 0);
            crow0 = ok0 ? (Cp + (size_t)a0 * ldc) : nullptr;
            crow1 = ok1 ? (Cp + (size_t)a1 * ldc) : nullptr;
        } else {
            crow0 = Cp + (size_t)gm0 * ldc;
            crow1 = Cp + (size_t)gm1 * ldc;
        }
#pragma unroll
        for (int ntile = 0; ntile < 4; ntile++) {
            const int cn = wn + ntile * 8 + 2 * l;
            long gn = n0 + cn;
            if (MODE == 3 && gn >= N) continue;
            float2 v0 = make_float2(acc[mt][ntile][0], acc[mt][ntile][1]);
            float2 v1 = make_float2(acc[mt][ntile][2], acc[mt][ntile][3]);
            if (MODE == 0 || MODE == 3) {
                float bx = bias[gn], by = bias[gn + 1];
                if (MODE == 0 && bias2) { bx += bias2[gn]; by += bias2[gn + 1]; }
                v0.x += bx; v0.y += by; v1.x += bx; v1.y += by;
            }
            if (ok0) *(float2*)(crow0 + gn) = v0;
            if (ok1) *(float2*)(crow1 + gn) = v1;
        }
    }
}

// ---------------------------------------------------------------------------
// Support kernels
// ---------------------------------------------------------------------------
__global__ void compact_rows(const int* __restrict__ lengths,
                             int* __restrict__ rowidx, int* __restrict__ mact)
{
    __shared__ int off[BB + 1];
    __shared__ int cnts[BB];
    int b = threadIdx.x;
    int cnt = min(lengths[b] + 1, TT);
    cnts[b] = cnt;
    __syncthreads();
    if (b == 0) {
        int s = 0;
        for (int i = 0; i < BB; i++) { off[i] = s; s += cnts[i]; }
        off[BB] = s;
        *mact = s;
    }
    __syncthreads();
    int o = off[b];
    for (int j = 0; j < cnt; j++) rowidx[o + j] = b * TT + j;
}

__global__ void zero_masked(const int* __restrict__ lengths, float* __restrict__ out)
{
    int r = blockIdx.x;
    int b = r / TT, t = r % TT;
    if (lengths[b] >= t) return;
    float4 zz = make_float4(0.f, 0.f, 0.f, 0.f);
    float4* row = (float4*)(out + (size_t)r * VV);
    for (int i = threadIdx.x; i < VV / 4; i += blockDim.x) row[i] = zz;
}

__global__ void gather_kernel(const int* __restrict__ cap,
                              const float* __restrict__ emb,
                              float* __restrict__ xe)
{
    int r = blockIdx.x;
    int i = threadIdx.x;
    const float4* src = (const float4*)(emb + (size_t)cap[r] * EE);
    ((float4*)(xe + (size_t)r * EE))[i] = src[i];
}

// ---------------------------------------------------------------------------
// Fused attention, 512 threads (16 warps) per batch row.
// a_h = b_h2a + sum of 4 hg partials (cols 4096+).
// ---------------------------------------------------------------------------
__global__ void __launch_bounds__(512)
attn_fused(const float* __restrict__ a_feat,
           const float* __restrict__ hg,
           const float* __restrict__ b_h2a,
           const float* __restrict__ w_a,
           const float* __restrict__ b_a,
           const float* __restrict__ feature,
           float* __restrict__ z)
{
    int b = blockIdx.x;
    int tid = threadIdx.x;
    int warp = tid >> 5, lane = tid & 31;
    __shared__ __align__(16) float s_ah[DD];
    __shared__ __align__(16) float s_w[DD];
    __shared__ float s_sc[FF];
    __shared__ __align__(16) float s_zp[4][DD];
    __shared__ float red[16];
    __shared__ float bmax, bsum;

    const size_t HGS = (size_t)BB * 4608;
    for (int i = tid; i < DD / 4; i += 512) {
        float4 v = ((const float4*)b_h2a)[i];
#pragma unroll
        for (int zp = 0; zp < 4; zp++) {
            float4 p = *(const float4*)(hg + (size_t)zp * HGS
                                        + (size_t)b * 4608 + 4096 + i * 4);
            v.x += p.x; v.y += p.y; v.z += p.z; v.w += p.w;
        }
        ((float4*)s_ah)[i] = v;
        ((float4*)s_w)[i]  = ((const float4*)w_a)[i];
    }
    __syncthreads();

    float ba = b_a[0];
    for (int f = warp; f < FF; f += 16) {
        const float4* af = (const float4*)(a_feat + ((size_t)b * FF + f) * DD);
        float s = 0.f;
#pragma unroll 4
        for (int k = lane; k < DD / 4; k += 32) {
            float4 a = af[k];
            float4 h4 = ((const float4*)s_ah)[k];
            float4 w4 = ((const float4*)s_w)[k];
            s += fmaxf(a.x + h4.x, 0.f) * w4.x
               + fmaxf(a.y + h4.y, 0.f) * w4.y
               + fmaxf(a.z + h4.z, 0.f) * w4.z
               + fmaxf(a.w + h4.w, 0.f) * w4.w;
        }
#pragma unroll
        for (int o = 16; o; o >>= 1) s += __shfl_down_sync(0xffffffffu, s, o);
        if (lane == 0) s_sc[f] = s + ba;
    }
    __syncthreads();

    // softmax over FF = 196
    float v = (tid < FF) ? s_sc[tid] : -3.0e38f;
    float m = v;
#pragma unroll
    for (int o = 16; o; o >>= 1) m = fmaxf(m, __shfl_xor_sync(0xffffffffu, m, o));
    if (lane == 0) red[warp] = m;
    __syncthreads();
    if (tid == 0) {
        float x = red[0];
        for (int w = 1; w < 16; w++) x = fmaxf(x, red[w]);
        bmax = x;
    }
    __syncthreads();
    float e = (tid < FF) ? expf(v - bmax) : 0.f;
    float s = e;
#pragma unroll
    for (int o = 16; o; o >>= 1) s += __shfl_xor_sync(0xffffffffu, s, o);
    if (lane == 0) red[warp] = s;
    __syncthreads();
    if (tid == 0) {
        float x = 0.f;
        for (int w = 0; w < 16; w++) x += red[w];
        bsum = x;
    }
    __syncthreads();
    if (tid < FF) s_sc[tid] = e / bsum;
    __syncthreads();

    // z phase: 4 quarters over f (49 each)
    {
        int quarter = tid >> 7;
        int dt = (tid & 127) * 4;
        int f0 = quarter * 49;
        int f1 = f0 + 49;
        const float4* fp = (const float4*)(feature + (size_t)b * FF * DD) + (dt >> 2);
        float a0 = 0.f, a1 = 0.f, a2 = 0.f, a3 = 0.f;
        for (int f = f0; f < f1; f++) {
            float4 q = fp[(size_t)f * (DD / 4)];
            float al = s_sc[f];
            a0 += al * q.x; a1 += al * q.y;
            a2 += al * q.z; a3 += al * q.w;
        }
        *(float4*)&s_zp[quarter][dt] = make_float4(a0, a1, a2, a3);
    }
    __syncthreads();
    if (tid < 128) {
        int dt = tid * 4;
        float4 u0 = *(const float4*)&s_zp[0][dt];
        float4 u1 = *(const float4*)&s_zp[1][dt];
        float4 u2 = *(const float4*)&s_zp[2][dt];
        float4 u3 = *(const float4*)&s_zp[3][dt];
        u0.x += u1.x + u2.x + u3.x;
        u0.y += u1.y + u2.y + u3.y;
        u0.z += u1.z + u2.z + u3.z;
        u0.w += u1.w + u2.w + u3.w;
        *(float4*)(z + (size_t)b * DD + dt) = u0;
    }
}

__global__ void zmean_kernel(const float* __restrict__ feature,
                             float* __restrict__ z)
{
    int b = blockIdx.x;
    int d = blockIdx.y * 128 + threadIdx.x;
    const float* fp = feature + (size_t)b * FF * DD + d;
    float s0 = 0.f, s1 = 0.f, s2 = 0.f, s3 = 0.f;
    for (int f = 0; f < FF; f += 4) {
        s0 += fp[(size_t)(f + 0) * DD];
        s1 += fp[(size_t)(f + 1) * DD];
        s2 += fp[(size_t)(f + 2) * DD];
        s3 += fp[(size_t)(f + 3) * DD];
    }
    z[b * DD + d] = ((s0 + s1) + (s2 + s3)) * (1.0f / FF);
}

__device__ __forceinline__ float sigmoidf_(float x) { return 1.f / (1.f + expf(-x)); }

// LSTM pointwise, float4-vectorized (4 hh per thread):
// gates = sum(2 zg partials) + sum(4 hg partials, cols 0..4096) + gemb.
__global__ void __launch_bounds__(256)
lstm_kernel(const float* __restrict__ zg,
            const float* __restrict__ hg,
            const float* __restrict__ gemb,
            const int* __restrict__ lengths, int t,
            float* __restrict__ h, float* __restrict__ c,
            float* __restrict__ hall)
{
    int idx = blockIdx.x * blockDim.x + threadIdx.x;   // BB*HH/4 threads
    int b = idx >> 8;                                  // HH/4 = 256
    int hh = (idx & 255) * 4;
    const size_t HGS = (size_t)BB * 4608;
    const size_t ZGS = (size_t)BB * 4096;
    const float* zgb = zg + (size_t)b * 4096;
    const float* hgb = hg + (size_t)b * 4608;
    const float* ge  = gemb + ((size_t)b * TT + t) * 4 * HH;

    float4 gate[4];
#pragma unroll
    for (int g = 0; g < 4; g++) {
        int col = g * HH + hh;
        float4 v = *(const float4*)(ge + col);
        float4 q0 = *(const float4*)(zgb + col);
        float4 q1 = *(const float4*)(zgb + ZGS + col);
        v.x += q0.x + q1.x; v.y += q0.y + q1.y;
        v.z += q0.z + q1.z; v.w += q0.w + q1.w;
#pragma unroll
        for (int zp = 0; zp < 4; zp++) {
            float4 p = *(const float4*)(hgb + (size_t)zp * HGS + col);
            v.x += p.x; v.y += p.y; v.z += p.z; v.w += p.w;
        }
        gate[g] = v;
    }

    float4 cv = *(const float4*)(c + (size_t)b * HH + hh);
    float4 cn, hn;
    {
        float ii, ff, gg, oo;
        ii = sigmoidf_(gate[0].x); ff = sigmoidf_(gate[1].x);
        gg = tanhf(gate[2].x);     oo = sigmoidf_(gate[3].x);
        cn.x = ff * cv.x + ii * gg; hn.x = oo * tanhf(cn.x);
        ii = sigmoidf_(gate[0].y); ff = sigmoidf_(gate[1].y);
        gg = tanhf(gate[2].y);     oo = sigmoidf_(gate[3].y);
        cn.y = ff * cv.y + ii * gg; hn.y = oo * tanhf(cn.y);
        ii = sigmoidf_(gate[0].z); ff = sigmoidf_(gate[1].z);
        gg = tanhf(gate[2].z);     oo = sigmoidf_(gate[3].z);
        cn.z = ff * cv.z + ii * gg; hn.z = oo * tanhf(cn.z);
        ii = sigmoidf_(gate[0].w); ff = sigmoidf_(gate[1].w);
        gg = tanhf(gate[2].w);     oo = sigmoidf_(gate[3].w);
        cn.w = ff * cv.w + ii * gg; hn.w = oo * tanhf(cn.w);
    }

    *(float4*)(hall + ((size_t)b * TT + t) * HH + hh) = hn;
    if (lengths[b] >= t) {
        *(float4*)(h + (size_t)b * HH + hh) = hn;
        *(float4*)(c + (size_t)b * HH + hh) = cn;
    }
}

// ---------------------------------------------------------------------------
// Host orchestration
// ---------------------------------------------------------------------------
extern "C" void kernel_launch(void* const* d_in, const int* in_sizes, int n_in,
                              void* d_out, int out_size)
{
    const float* feature = (const float*)d_in[0];
    const int*   captions = (const int*)d_in[1];
    const int*   lengths = (const int*)d_in[2];
    const float* emb    = (const float*)d_in[3];
    const float* W_ih   = (const float*)d_in[4];
    const float* b_ih   = (const float*)d_in[5];
    const float* W_hh   = (const float*)d_in[6];
    const float* b_hh   = (const float*)d_in[7];
    const float* W_fc   = (const float*)d_in[8];
    const float* b_fc   = (const float*)d_in[9];
    const float* W_h2a  = (const float*)d_in[10];
    const float* b_h2a  = (const float*)d_in[11];
    const float* W_f2a  = (const float*)d_in[12];
    const float* b_f2a  = (const float*)d_in[13];
    const float* W_a2a  = (const float*)d_in[14];
    const float* b_a2a  = (const float*)d_in[15];
    float* out = (float*)d_out;

    float *a_feat, *x_e, *gemb, *hall, *h, *c, *z, *z0, *hg, *zg;
    int *rowidx, *mact;
    cudaGetSymbolAddress((void**)&a_feat, g_a_feat);
    cudaGetSymbolAddress((void**)&x_e,    g_x_emb);
    cudaGetSymbolAddress((void**)&gemb,   g_gemb);
    cudaGetSymbolAddress((void**)&hall,   g_hall);
    cudaGetSymbolAddress((void**)&h,      g_h);
    cudaGetSymbolAddress((void**)&c,      g_c);
    cudaGetSymbolAddress((void**)&z,      g_z);
    cudaGetSymbolAddress((void**)&z0,     g_z0);
    cudaGetSymbolAddress((void**)&hg,     g_hg);
    cudaGetSymbolAddress((void**)&zg,     g_zg);
    cudaGetSymbolAddress((void**)&rowidx, g_rowidx);
    cudaGetSymbolAddress((void**)&mact,   g_mact);

    static cudaStream_t s1 = nullptr;
    static cudaEvent_t evFork = nullptr, evA = nullptr;
    if (s1 == nullptr) {
        cudaStreamCreateWithFlags(&s1, cudaStreamNonBlocking);
        cudaEventCreateWithFlags(&evFork, cudaEventDisableTiming);
        cudaEventCreateWithFlags(&evA,    cudaEventDisableTiming);
    }

    cudaMemsetAsync(h,  0, (size_t)BB * HH * sizeof(float));
    cudaMemsetAsync(c,  0, (size_t)BB * HH * sizeof(float));
    cudaMemsetAsync(hg, 0, (size_t)4 * BB * 4608 * sizeof(float));
    gather_kernel<<<BB * TT, 128>>>(captions, emb, x_e);
    compact_rows<<<1, BB>>>(lengths, rowidx, mact);

    // Side stream: a_feat GEMM + zero_masked
    cudaEventRecord(evFork, 0);
    cudaStreamWaitEvent(s1, evFork, 0);
    mma_gemm<0><<<dim3(196, 4), 256, 0, s1>>>(
        feature, DD, W_f2a, DD, nullptr,
        b_f2a, nullptr,
        a_feat, DD, BB * FF, DD, DD, nullptr, nullptr);
    zero_masked<<<BB * TT, 256, 0, s1>>>(lengths, out);
    cudaEventRecord(evA, s1);

    // g_emb = x_emb @ W_ih[:, D:]^T + b_ih + b_hh   [2560, 512] x [4096, 512]
    mma_gemm<0><<<dim3(20, 32), 256>>>(
        x_e, EE, W_ih + DD, DD + EE, nullptr,
        b_ih, b_hh,
        gemb, 4 * HH, BB * TT, 4 * HH, EE, nullptr, nullptr);

    zmean_kernel<<<dim3(BB, DD / 128), 128>>>(feature, z0);

    for (int t = 0; t < TT; t++) {
        if (t > 0) {
            // hg = h @ [W_hh | W_h2a]^T, split-K=4 partials [4][128][4608]
            mma_gemm<7><<<dim3(1, 36, 4), 256>>>(
                h, HH, W_hh, HH, W_h2a,
                nullptr, nullptr,
                hg, 4608, BB, 4608, 256, nullptr, nullptr);

            if (t == 1) cudaStreamWaitEvent(0, evA, 0);  // a_feat ready
            attn_fused<<<BB, 512>>>(a_feat, hg, b_h2a, W_a2a, b_a2a, feature, z);
        }

        // zg = z @ W_ih[:, :512]^T, split-K=2 partials [2][128][4096]
        mma_gemm<5><<<dim3(1, 32, 2), 256>>>(
            (t == 0) ? z0 : z, DD, W_ih, DD + EE, nullptr,
            nullptr, nullptr,
            zg, 4 * HH, BB, 4 * HH, 256, nullptr, nullptr);

        lstm_kernel<<<(BB * HH / 4) / 256, 256>>>(zg, hg, gemb, lengths, t,
                                                  h, c, hall);
    }

    // preds[active rows] = h_all @ W_fc^T + b_fc    [Mact, 1024] x [10000, 1024]
    mma_gemm<3><<<dim3(20, 79), 256>>>(
        hall, HH, W_fc, HH, nullptr,
        b_fc, nullptr,
        out, VV, BB * TT, VV, HH, rowidx, mact);
}